// round 1
// baseline (speedup 1.0000x reference)
#include <cuda_runtime.h>
#include <math.h>

#define NTASK 64
#define NB    4096
#define TD    512
#define HD    256
#define VD    484
#define BT    64      // batch rows per CTA
#define KC    32      // k-chunk staged in smem
#define ASTR  65      // Ast row stride (conflict-free transpose stores)
#define HSP   260     // hs row stride (floats, 16B-aligned rows)
#define NC2   128     // n-chunk for GEMM2

typedef unsigned long long ull;

struct SmemLayout {
    float Ast[KC][ASTR];        // t_feat tile, [k][m]
    union {
        float Bs[KC][HD];       // W1 tile, [k][n]
        float W2s[KC][NC2];     // W2 tile, [k][n_local]
    };
    float hs[BT][HSP];          // hidden activations
};

__device__ __forceinline__ ull pk2(float lo, float hi) {
    ull r;
    asm("mov.b64 %0, {%1, %2};" : "=l"(r) : "f"(lo), "f"(hi));
    return r;
}
__device__ __forceinline__ void upk2(ull v, float& lo, float& hi) {
    asm("mov.b64 {%0, %1}, %2;" : "=f"(lo), "=f"(hi) : "l"(v));
}
__device__ __forceinline__ void ffma2(ull& d, ull a, ull b) {
#if defined(__CUDA_ARCH__) && (__CUDA_ARCH__ >= 1000)
    asm("fma.rn.f32x2 %0, %1, %2, %0;" : "+l"(d) : "l"(a), "l"(b));
#else
    float dl, dh, al, ah, bl, bh;
    upk2(d, dl, dh); upk2(a, al, ah); upk2(b, bl, bh);
    d = pk2(fmaf(al, bl, dl), fmaf(ah, bh, dh));
#endif
}

__global__ void __launch_bounds__(256, 1)
router_kernel(const float* __restrict__ t_feat,
              const float* __restrict__ W1,
              const float* __restrict__ b1,
              const float* __restrict__ gamma,
              const float* __restrict__ beta,
              const float* __restrict__ W2,
              const float* __restrict__ b2,
              const float* __restrict__ cent,
              float* __restrict__ out, int out_size)
{
    extern __shared__ char smem_raw[];
    SmemLayout& s = *reinterpret_cast<SmemLayout*>(smem_raw);

    const int tid  = threadIdx.x;
    const int tn   = tid & 31;         // lane
    const int wid  = tid >> 5;         // warp 0..7
    const int m0   = wid * 8;          // this warp's 8 rows
    const int task = blockIdx.y;
    const int brow0 = blockIdx.x * BT;

    // ================= GEMM1: h[m][n] = sum_k t_feat[m][k] * W1[t][n][k] =================
    ull acc[4][8];
#pragma unroll
    for (int p = 0; p < 4; ++p)
#pragma unroll
        for (int j = 0; j < 8; ++j) acc[p][j] = 0ULL;

    const float* W1t = W1 + (size_t)task * HD * TD;
    const int arow = tid >> 2;          // 0..63
    const int ak0  = (tid & 3) * 8;     // 0,8,16,24

    for (int kc = 0; kc < TD; kc += KC) {
        // stage A (transposed): Ast[k][m]
#pragma unroll
        for (int u = 0; u < 2; ++u) {
            float4 v = *reinterpret_cast<const float4*>(
                &t_feat[(size_t)(brow0 + arow) * TD + kc + ak0 + u * 4]);
            int kk = ak0 + u * 4;
            s.Ast[kk + 0][arow] = v.x; s.Ast[kk + 1][arow] = v.y;
            s.Ast[kk + 2][arow] = v.z; s.Ast[kk + 3][arow] = v.w;
        }
        // stage B (transposed): Bs[k][n], n = tid
#pragma unroll
        for (int u = 0; u < 8; ++u) {
            float4 v = *reinterpret_cast<const float4*>(
                &W1t[(size_t)tid * TD + kc + u * 4]);
            int kk = u * 4;
            s.Bs[kk + 0][tid] = v.x; s.Bs[kk + 1][tid] = v.y;
            s.Bs[kk + 2][tid] = v.z; s.Bs[kk + 3][tid] = v.w;
        }
        __syncthreads();
#pragma unroll 8
        for (int k = 0; k < KC; ++k) {
            ull a[4];
#pragma unroll
            for (int p = 0; p < 4; ++p)
                a[p] = pk2(s.Ast[k][m0 + 2 * p], s.Ast[k][m0 + 2 * p + 1]);
            float4 bA = *reinterpret_cast<const float4*>(&s.Bs[k][tn * 4]);
            float4 bB = *reinterpret_cast<const float4*>(&s.Bs[k][128 + tn * 4]);
            ull b[8];
            b[0] = pk2(bA.x, bA.x); b[1] = pk2(bA.y, bA.y);
            b[2] = pk2(bA.z, bA.z); b[3] = pk2(bA.w, bA.w);
            b[4] = pk2(bB.x, bB.x); b[5] = pk2(bB.y, bB.y);
            b[6] = pk2(bB.z, bB.z); b[7] = pk2(bB.w, bB.w);
#pragma unroll
            for (int p = 0; p < 4; ++p)
#pragma unroll
                for (int j = 0; j < 8; ++j)
                    ffma2(acc[p][j], a[p], b[j]);
        }
        __syncthreads();
    }

    // GEMM1 epilogue: + b1, store to hs
    {
        float b1A[4], b1B[4];
#pragma unroll
        for (int j = 0; j < 4; ++j) {
            b1A[j] = b1[task * HD + tn * 4 + j];
            b1B[j] = b1[task * HD + 128 + tn * 4 + j];
        }
#pragma unroll
        for (int p = 0; p < 4; ++p) {
            float lo[8], hi[8];
#pragma unroll
            for (int j = 0; j < 8; ++j) upk2(acc[p][j], lo[j], hi[j]);
            float4 vA0 = make_float4(lo[0] + b1A[0], lo[1] + b1A[1], lo[2] + b1A[2], lo[3] + b1A[3]);
            float4 vB0 = make_float4(lo[4] + b1B[0], lo[5] + b1B[1], lo[6] + b1B[2], lo[7] + b1B[3]);
            float4 vA1 = make_float4(hi[0] + b1A[0], hi[1] + b1A[1], hi[2] + b1A[2], hi[3] + b1A[3]);
            float4 vB1 = make_float4(hi[4] + b1B[0], hi[5] + b1B[1], hi[6] + b1B[2], hi[7] + b1B[3]);
            *reinterpret_cast<float4*>(&s.hs[m0 + 2 * p][tn * 4])           = vA0;
            *reinterpret_cast<float4*>(&s.hs[m0 + 2 * p][128 + tn * 4])     = vB0;
            *reinterpret_cast<float4*>(&s.hs[m0 + 2 * p + 1][tn * 4])       = vA1;
            *reinterpret_cast<float4*>(&s.hs[m0 + 2 * p + 1][128 + tn * 4]) = vB1;
        }
    }
    __syncthreads();

    // ================= LayerNorm + exact GELU (row per warp-iteration) =================
#pragma unroll 1
    for (int r = 0; r < 8; ++r) {
        const int m = m0 + r;
        float x[8];
#pragma unroll
        for (int i = 0; i < 8; ++i) x[i] = s.hs[m][tn + 32 * i];
        float sum = 0.f;
#pragma unroll
        for (int i = 0; i < 8; ++i) sum += x[i];
#pragma unroll
        for (int o = 16; o > 0; o >>= 1) sum += __shfl_xor_sync(0xffffffffu, sum, o);
        const float mu = sum * (1.0f / HD);
        float vs = 0.f;
#pragma unroll
        for (int i = 0; i < 8; ++i) { float d = x[i] - mu; vs += d * d; }
#pragma unroll
        for (int o = 16; o > 0; o >>= 1) vs += __shfl_xor_sync(0xffffffffu, vs, o);
        const float rstd = rsqrtf(vs * (1.0f / HD) + 1e-5f);
#pragma unroll
        for (int i = 0; i < 8; ++i) {
            const int n = tn + 32 * i;
            float y = (x[i] - mu) * rstd * gamma[task * HD + n] + beta[task * HD + n];
            y = 0.5f * y * (1.0f + erff(y * 0.70710678118654752440f));
            s.hs[m][n] = y;
        }
    }
    __syncthreads();

    // ================= GEMM2 + cosine epilogue (v never materialized) =================
    float vcp[8], vvp[8];
#pragma unroll
    for (int r = 0; r < 8; ++r) { vcp[r] = 0.f; vvp[r] = 0.f; }

    const float* W2t = W2 + (size_t)task * VD * HD;
    const int wn  = tid >> 1;          // 0..127
    const int wk0 = (tid & 1) * 16;

    for (int nc = 0; nc < 4; ++nc) {
        const int nbase = nc * NC2;
        ull acc2[4][4];
#pragma unroll
        for (int p = 0; p < 4; ++p)
#pragma unroll
            for (int j = 0; j < 4; ++j) acc2[p][j] = 0ULL;

        for (int kc = 0; kc < HD; kc += KC) {
            __syncthreads();   // protect W2s from previous readers
            const int gn = nbase + wn;
            if (gn < VD) {
#pragma unroll
                for (int u = 0; u < 4; ++u) {
                    float4 v = *reinterpret_cast<const float4*>(
                        &W2t[(size_t)gn * HD + kc + wk0 + u * 4]);
                    int kk = wk0 + u * 4;
                    s.W2s[kk + 0][wn] = v.x; s.W2s[kk + 1][wn] = v.y;
                    s.W2s[kk + 2][wn] = v.z; s.W2s[kk + 3][wn] = v.w;
                }
            } else {
#pragma unroll
                for (int u = 0; u < 16; ++u) s.W2s[wk0 + u][wn] = 0.0f;
            }
            __syncthreads();
#pragma unroll 8
            for (int k = 0; k < KC; ++k) {
                const int kg = kc + k;
                ull a[4];
#pragma unroll
                for (int p = 0; p < 4; ++p)
                    a[p] = pk2(s.hs[m0 + 2 * p][kg], s.hs[m0 + 2 * p + 1][kg]);
                float4 bv = *reinterpret_cast<const float4*>(&s.W2s[k][tn * 4]);
                ull b[4];
                b[0] = pk2(bv.x, bv.x); b[1] = pk2(bv.y, bv.y);
                b[2] = pk2(bv.z, bv.z); b[3] = pk2(bv.w, bv.w);
#pragma unroll
                for (int p = 0; p < 4; ++p)
#pragma unroll
                    for (int j = 0; j < 4; ++j)
                        ffma2(acc2[p][j], a[p], b[j]);
            }
        }
        // chunk epilogue: fold b2, accumulate v.c and v.v per row
#pragma unroll
        for (int j = 0; j < 4; ++j) {
            const int n = nbase + tn * 4 + j;
            if (n < VD) {
                const float bb = b2[task * VD + n];
                const float cc = cent[task * VD + n];
#pragma unroll
                for (int p = 0; p < 4; ++p) {
                    float lo, hi; upk2(acc2[p][j], lo, hi);
                    const float v0 = lo + bb, v1 = hi + bb;
                    vcp[2 * p]     += v0 * cc;  vvp[2 * p]     += v0 * v0;
                    vcp[2 * p + 1] += v1 * cc;  vvp[2 * p + 1] += v1 * v1;
                }
            }
        }
    }

    // warp-reduce the 8-row partials
#pragma unroll
    for (int o = 16; o > 0; o >>= 1) {
#pragma unroll
        for (int r = 0; r < 8; ++r) {
            vcp[r] += __shfl_xor_sync(0xffffffffu, vcp[r], o);
            vvp[r] += __shfl_xor_sync(0xffffffffu, vvp[r], o);
        }
    }

    // centroid norm (redundant per warp, negligible)
    float cn2 = 0.f;
    for (int n = tn; n < VD; n += 32) { float c = cent[task * VD + n]; cn2 += c * c; }
#pragma unroll
    for (int o = 16; o > 0; o >>= 1) cn2 += __shfl_xor_sync(0xffffffffu, cn2, o);
    const float cn = fmaxf(sqrtf(cn2), 1e-8f);

    // lane r<8 handles row m0+r (static-index selection, no local-mem spill)
    float vc_sel = vcp[0], vv_sel = vvp[0];
#pragma unroll
    for (int r = 1; r < 8; ++r) if (tn == r) { vc_sel = vcp[r]; vv_sel = vvp[r]; }
    float part = 0.f;
    if (tn < 8) {
        const float vn = fmaxf(sqrtf(vv_sel), 1e-8f);
        part = 1.0f - vc_sel / (vn * cn);
    }
#pragma unroll
    for (int o = 16; o > 0; o >>= 1) part += __shfl_xor_sync(0xffffffffu, part, o);
    if (tn == 0 && task < out_size) atomicAdd(&out[task], part);
}

__global__ void zero_kernel(float* __restrict__ out, int out_size) {
    int i = threadIdx.x;
    if (i < 64 && i < out_size) out[i] = 0.0f;
}

__global__ void finalize_kernel(float* __restrict__ out, int out_size) {
    __shared__ float d[64];
    const int t = threadIdx.x;
    float v = 0.0f;
    if (t < out_size) {
        v = out[t] * (1.0f / (float)NB);
        out[t] = v;
    }
    d[t] = v;
    __syncthreads();
    if (t == 0) {
        int best = 0; float bv = d[0];
#pragma unroll 1
        for (int i = 1; i < 64; ++i) {
            if (d[i] < bv) { bv = d[i]; best = i; }
        }
        if (out_size > 64) out[64] = (float)best;
    }
}

extern "C" void kernel_launch(void* const* d_in, const int* in_sizes, int n_in,
                              void* d_out, int out_size) {
    const float* t_feat = (const float*)d_in[0];
    const float* W1     = (const float*)d_in[1];
    const float* b1     = (const float*)d_in[2];
    const float* gamma  = (const float*)d_in[3];
    const float* beta   = (const float*)d_in[4];
    const float* W2     = (const float*)d_in[5];
    const float* b2     = (const float*)d_in[6];
    const float* cent   = (const float*)d_in[7];
    float* out = (float*)d_out;

    cudaFuncSetAttribute(router_kernel,
                         cudaFuncAttributeMaxDynamicSharedMemorySize,
                         (int)sizeof(SmemLayout));

    zero_kernel<<<1, 64>>>(out, out_size);
    dim3 grid(NB / BT, NTASK);
    router_kernel<<<grid, 256, sizeof(SmemLayout)>>>(
        t_feat, W1, b1, gamma, beta, W2, b2, cent, out, out_size);
    finalize_kernel<<<1, 64>>>(out, out_size);
}

// round 4
// speedup vs baseline: 4.6994x; 4.6994x over previous
#include <cuda_runtime.h>
#include <cstdint>
#include <math.h>

#define NTASK 64
#define NB    4096
#define TD    512
#define HD    256
#define VD    484
#define MT    128
#define KC    16
#define STR   20          // staged-tile row stride (floats): conflict-free
#define HSTR  260         // h row stride (floats): conflict-free ldmatrix
#define THREADS 512

// ---- smem layout (bytes) ----
#define SM_H      0
#define SM_STAGE  (MT * HSTR * 4)               // 133120
#define STAGE_BUF 30720                          // A(10240) + B(20480)
#define SM_PARB   (SM_STAGE + 2 * STAGE_BUF)     // 194560
// param floats: b1s 256 | gms 256 | bts 256 | b2s 512 | cts 512 |
//               rowSum 128 | rowSq 128 | vcA 128 | vvA 128 | red 32  = 2336 floats
#define SMEM_TOTAL (SM_PARB + 2336 * 4)          // 203904

__device__ __forceinline__ uint32_t s2u(const void* p) {
    uint32_t a;
    asm("{ .reg .u64 t; cvta.to.shared.u64 t, %1; cvt.u32.u64 %0, t; }" : "=r"(a) : "l"(p));
    return a;
}
__device__ __forceinline__ void cp16(uint32_t dst, const void* src) {
    asm volatile("cp.async.cg.shared.global [%0], [%1], 16;" :: "r"(dst), "l"(src) : "memory");
}
__device__ __forceinline__ void cpcommit() { asm volatile("cp.async.commit_group;" ::: "memory"); }
__device__ __forceinline__ void cpwait1()  { asm volatile("cp.async.wait_group 1;" ::: "memory"); }
__device__ __forceinline__ void cpwait0()  { asm volatile("cp.async.wait_group 0;" ::: "memory"); }

__device__ __forceinline__ void ldsm4(uint32_t* r, uint32_t a) {
    asm volatile("ldmatrix.sync.aligned.m8n8.x4.shared.b16 {%0,%1,%2,%3}, [%4];"
                 : "=r"(r[0]), "=r"(r[1]), "=r"(r[2]), "=r"(r[3]) : "r"(a));
}
__device__ __forceinline__ void mma8(float* c, const uint32_t* a, uint32_t b0, uint32_t b1) {
    asm volatile(
        "mma.sync.aligned.m16n8k8.row.col.f32.tf32.tf32.f32 "
        "{%0,%1,%2,%3}, {%4,%5,%6,%7}, {%8,%9}, {%0,%1,%2,%3};"
        : "+f"(c[0]), "+f"(c[1]), "+f"(c[2]), "+f"(c[3])
        : "r"(a[0]), "r"(a[1]), "r"(a[2]), "r"(a[3]), "r"(b0), "r"(b1));
}
__device__ __forceinline__ void stv2(uint32_t a, float x, float y) {
    asm volatile("st.shared.v2.f32 [%0], {%1,%2};" :: "r"(a), "f"(x), "f"(y) : "memory");
}
__device__ __forceinline__ void stz4(uint32_t a) {
    asm volatile("st.shared.v4.b32 [%0], {%1,%1,%1,%1};" :: "r"(a), "r"(0u) : "memory");
}

__global__ void __launch_bounds__(THREADS, 1)
router_mma_kernel(const float* __restrict__ t_feat,
                  const float* __restrict__ W1,
                  const float* __restrict__ b1,
                  const float* __restrict__ gamma,
                  const float* __restrict__ beta,
                  const float* __restrict__ W2,
                  const float* __restrict__ b2,
                  const float* __restrict__ cent,
                  float* __restrict__ out, int out_size)
{
    extern __shared__ char smem[];
    const uint32_t sb = s2u(smem);
    const int tid  = threadIdx.x;
    const int lane = tid & 31;
    const int wid  = tid >> 5;
    const int wm   = wid & 3,  wn = wid >> 2;
    const int m0w  = wm * 32,  n0w = wn * 64;
    const int task = blockIdx.y;
    const int brow0 = blockIdx.x * MT;

    const float* tA  = t_feat + (size_t)brow0 * TD;
    const float* W1t = W1 + (size_t)task * HD * TD;
    const float* W2t = W2 + (size_t)task * VD * HD;

    float* b1s    = (float*)(smem + SM_PARB);
    float* gms    = b1s + 256;
    float* bts    = gms + 256;
    float* b2s    = bts + 256;     // 512
    float* cts    = b2s + 512;     // 512
    float* rowSum = cts + 512;     // 128
    float* rowSq  = rowSum + 128;  // 128
    float* vcA    = rowSq + 128;   // 128
    float* vvA    = vcA + 128;     // 128
    float* red    = vvA + 128;     // 32

    // ldmatrix per-lane address components
    const int arow = lane & 15;
    const int acol = (lane >> 4) * 4;
    const int brow = ((lane >> 4) << 3) | (lane & 7);
    const int bcol = ((lane >> 3) & 1) * 4;

    // ---- prefetch GEMM1 chunk 0 ----
    {
        const uint32_t ab = sb + SM_STAGE;
        const uint32_t bb = ab + 10240;
        { const int row = tid >> 2, s = tid & 3;
          cp16(ab + (uint32_t)(row * STR + s * 4) * 4, tA + (size_t)row * TD + s * 4); }
#pragma unroll
        for (int i = 0; i < 2; ++i) {
            const int seg = tid + 512 * i, row = seg >> 2, s = seg & 3;
            cp16(bb + (uint32_t)(row * STR + s * 4) * 4, W1t + (size_t)row * TD + s * 4);
        }
        cpcommit();
    }

    // ---- params + zeros (overlap with cp.async) ----
    if (tid < 256) {
        b1s[tid] = b1[task * HD + tid];
        gms[tid] = gamma[task * HD + tid];
        bts[tid] = beta[task * HD + tid];
    }
    {
        float bv = 0.f, cv = 0.f;
        if (tid < VD) { bv = b2[task * VD + tid]; cv = cent[task * VD + tid]; }
        b2s[tid] = bv; cts[tid] = cv;
        float ce = cv * cv;
#pragma unroll
        for (int o = 16; o > 0; o >>= 1) ce += __shfl_xor_sync(0xffffffffu, ce, o);
        if (lane == 0) red[wid] = ce;
    }
    if (tid < 128) { rowSum[tid] = 0.f; rowSq[tid] = 0.f; vcA[tid] = 0.f; vvA[tid] = 0.f; }

    float acc[2][8][4];
#pragma unroll
    for (int mb = 0; mb < 2; ++mb)
#pragma unroll
        for (int q = 0; q < 8; ++q)
#pragma unroll
            for (int c = 0; c < 4; ++c) acc[mb][q][c] = 0.f;

    // ================= GEMM1: K=512, 32 chunks =================
    for (int c = 0; c < 32; ++c) {
        if (c < 31) {
            const int kb = (c + 1) * KC;
            const uint32_t ab = sb + SM_STAGE + (uint32_t)((c + 1) & 1) * STAGE_BUF;
            const uint32_t bb = ab + 10240;
            { const int row = tid >> 2, s = tid & 3;
              cp16(ab + (uint32_t)(row * STR + s * 4) * 4, tA + (size_t)row * TD + kb + s * 4); }
#pragma unroll
            for (int i = 0; i < 2; ++i) {
                const int seg = tid + 512 * i, row = seg >> 2, s = seg & 3;
                cp16(bb + (uint32_t)(row * STR + s * 4) * 4, W1t + (size_t)row * TD + kb + s * 4);
            }
            cpcommit();
            cpwait1();
        } else {
            cpwait0();
        }
        __syncthreads();
        const uint32_t ab = sb + SM_STAGE + (uint32_t)(c & 1) * STAGE_BUF;
        const uint32_t bb = ab + 10240;
#pragma unroll
        for (int ks = 0; ks < 2; ++ks) {
            uint32_t a[2][4];
#pragma unroll
            for (int mb = 0; mb < 2; ++mb)
                ldsm4(a[mb], ab + (uint32_t)((m0w + mb * 16 + arow) * STR + ks * 8 + acol) * 4);
#pragma unroll
            for (int q = 0; q < 4; ++q) {
                uint32_t bq[4];
                ldsm4(bq, bb + (uint32_t)((n0w + q * 16 + brow) * STR + ks * 8 + bcol) * 4);
#pragma unroll
                for (int mb = 0; mb < 2; ++mb) {
                    mma8(acc[mb][2 * q],     a[mb], bq[0], bq[1]);
                    mma8(acc[mb][2 * q + 1], a[mb], bq[2], bq[3]);
                }
            }
        }
        __syncthreads();
    }

    // ================= LayerNorm stats (cross-warp via smem atomics) =================
    {
        float sums[4] = {0.f, 0.f, 0.f, 0.f}, sqs[4] = {0.f, 0.f, 0.f, 0.f};
#pragma unroll
        for (int mb = 0; mb < 2; ++mb)
#pragma unroll
            for (int q = 0; q < 8; ++q)
#pragma unroll
                for (int c = 0; c < 4; ++c) {
                    const int n = n0w + q * 8 + 2 * (lane & 3) + (c & 1);
                    const float x = acc[mb][q][c] + b1s[n];
                    acc[mb][q][c] = x;
                    const int key = (mb << 1) | (c >> 1);
                    sums[key] += x;
                    sqs[key]  = fmaf(x, x, sqs[key]);
                }
#pragma unroll
        for (int o = 1; o <= 2; o <<= 1)
#pragma unroll
            for (int k = 0; k < 4; ++k) {
                sums[k] += __shfl_xor_sync(0xffffffffu, sums[k], o);
                sqs[k]  += __shfl_xor_sync(0xffffffffu, sqs[k], o);
            }
        if ((lane & 3) == 0) {
#pragma unroll
            for (int k = 0; k < 4; ++k) {
                const int r = m0w + (k >> 1) * 16 + (k & 1) * 8 + (lane >> 2);
                atomicAdd(&rowSum[r], sums[k]);
                atomicAdd(&rowSq[r],  sqs[k]);
            }
        }
    }
    __syncthreads();

    // ================= normalize + exact GELU + store h =================
#pragma unroll
    for (int mb = 0; mb < 2; ++mb)
#pragma unroll
        for (int cp = 0; cp < 2; ++cp) {
            const int r = m0w + mb * 16 + cp * 8 + (lane >> 2);
            const float mu   = rowSum[r] * (1.0f / HD);
            const float var  = rowSq[r] * (1.0f / HD) - mu * mu;
            const float rstd = rsqrtf(var + 1e-5f);
#pragma unroll
            for (int q = 0; q < 8; ++q) {
                const int n = n0w + q * 8 + 2 * (lane & 3);
                float y0 = (acc[mb][q][cp * 2]     - mu) * rstd * gms[n]     + bts[n];
                float y1 = (acc[mb][q][cp * 2 + 1] - mu) * rstd * gms[n + 1] + bts[n + 1];
                y0 = 0.5f * y0 * (1.0f + erff(y0 * 0.70710678118654752440f));
                y1 = 0.5f * y1 * (1.0f + erff(y1 * 0.70710678118654752440f));
                stv2(sb + SM_H + (uint32_t)(r * HSTR + n) * 4, y0, y1);
            }
        }
    // (h visibility to GEMM2 covered by the syncthreads inside the GEMM2 loop)

    // ================= GEMM2 + cosine epilogue =================
    float vc4[4] = {0.f, 0.f, 0.f, 0.f}, vv4[4] = {0.f, 0.f, 0.f, 0.f};

    for (int half = 0; half < 2; ++half) {
#pragma unroll
        for (int mb = 0; mb < 2; ++mb)
#pragma unroll
            for (int q = 0; q < 8; ++q)
#pragma unroll
                for (int c = 0; c < 4; ++c) acc[mb][q][c] = 0.f;

        // prefetch chunk 0
        {
            const uint32_t bb = sb + SM_STAGE;
#pragma unroll
            for (int i = 0; i < 2; ++i) {
                const int seg = tid + 512 * i, row = seg >> 2, s = seg & 3;
                const int n = half * 256 + row;
                const uint32_t dst = bb + (uint32_t)(row * STR + s * 4) * 4;
                if (n < VD) cp16(dst, W2t + (size_t)n * HD + s * 4);
                else        stz4(dst);
            }
            cpcommit();
        }
        for (int c = 0; c < 16; ++c) {
            if (c < 15) {
                const int kb = (c + 1) * KC;
                const uint32_t bb = sb + SM_STAGE + (uint32_t)((c + 1) & 1) * STAGE_BUF;
#pragma unroll
                for (int i = 0; i < 2; ++i) {
                    const int seg = tid + 512 * i, row = seg >> 2, s = seg & 3;
                    const int n = half * 256 + row;
                    const uint32_t dst = bb + (uint32_t)(row * STR + s * 4) * 4;
                    if (n < VD) cp16(dst, W2t + (size_t)n * HD + kb + s * 4);
                    else        stz4(dst);
                }
                cpcommit();
                cpwait1();
            } else {
                cpwait0();
            }
            __syncthreads();
            const uint32_t bb = sb + SM_STAGE + (uint32_t)(c & 1) * STAGE_BUF;
            const int kb = c * KC;
#pragma unroll
            for (int ks = 0; ks < 2; ++ks) {
                uint32_t a[2][4];
#pragma unroll
                for (int mb = 0; mb < 2; ++mb)
                    ldsm4(a[mb], sb + SM_H +
                          (uint32_t)((m0w + mb * 16 + arow) * HSTR + kb + ks * 8 + acol) * 4);
#pragma unroll
                for (int q = 0; q < 4; ++q) {
                    uint32_t bq[4];
                    ldsm4(bq, bb + (uint32_t)((n0w + q * 16 + brow) * STR + ks * 8 + bcol) * 4);
#pragma unroll
                    for (int mb = 0; mb < 2; ++mb) {
                        mma8(acc[mb][2 * q],     a[mb], bq[0], bq[1]);
                        mma8(acc[mb][2 * q + 1], a[mb], bq[2], bq[3]);
                    }
                }
            }
            __syncthreads();
        }
        // fold b2 + centroid into per-row partials (v never materialized)
#pragma unroll
        for (int mb = 0; mb < 2; ++mb)
#pragma unroll
            for (int q = 0; q < 8; ++q)
#pragma unroll
                for (int c = 0; c < 4; ++c) {
                    const int n = half * 256 + n0w + q * 8 + 2 * (lane & 3) + (c & 1);
                    const float v = acc[mb][q][c] + b2s[n];
                    const int key = (mb << 1) | (c >> 1);
                    vc4[key] = fmaf(v, cts[n], vc4[key]);
                    vv4[key] = fmaf(v, v,     vv4[key]);
                }
    }

#pragma unroll
    for (int o = 1; o <= 2; o <<= 1)
#pragma unroll
        for (int k = 0; k < 4; ++k) {
            vc4[k] += __shfl_xor_sync(0xffffffffu, vc4[k], o);
            vv4[k] += __shfl_xor_sync(0xffffffffu, vv4[k], o);
        }
    if ((lane & 3) == 0) {
#pragma unroll
        for (int k = 0; k < 4; ++k) {
            const int r = m0w + (k >> 1) * 16 + (k & 1) * 8 + (lane >> 2);
            atomicAdd(&vcA[r], vc4[k]);
            atomicAdd(&vvA[r], vv4[k]);
        }
    }
    __syncthreads();

    // ---- per-row cosine distance, block reduce, one atomic per CTA ----
    float dist = 0.f;
    if (tid < 128) {
        float cn2 = 0.f;
#pragma unroll
        for (int i = 0; i < 16; ++i) cn2 += red[i];
        const float cn = fmaxf(sqrtf(cn2), 1e-8f);
        const float vn = fmaxf(sqrtf(vvA[tid]), 1e-8f);
        dist = 1.0f - vcA[tid] / (vn * cn);
    }
#pragma unroll
    for (int o = 16; o > 0; o >>= 1) dist += __shfl_xor_sync(0xffffffffu, dist, o);
    if (tid < 128 && lane == 0) red[16 + wid] = dist;
    __syncthreads();
    if (tid == 0 && task < out_size) {
        atomicAdd(&out[task], red[16] + red[17] + red[18] + red[19]);
    }
}

__global__ void zero_kernel(float* __restrict__ out, int out_size) {
    const int i = threadIdx.x;
    if (i < 64 && i < out_size) out[i] = 0.0f;
}

__global__ void finalize_kernel(float* __restrict__ out, int out_size) {
    __shared__ float d[64];
    const int t = threadIdx.x;
    float v = 0.0f;
    if (t < out_size) {
        v = out[t] * (1.0f / (float)NB);
        out[t] = v;
    }
    d[t] = v;
    __syncthreads();
    if (t == 0) {
        int best = 0;
        float bv = d[0];
#pragma unroll 1
        for (int i = 1; i < 64; ++i)
            if (d[i] < bv) { bv = d[i]; best = i; }
        if (out_size > 64) out[64] = (float)best;
    }
}

extern "C" void kernel_launch(void* const* d_in, const int* in_sizes, int n_in,
                              void* d_out, int out_size) {
    const float* t_feat = (const float*)d_in[0];
    const float* W1     = (const float*)d_in[1];
    const float* b1     = (const float*)d_in[2];
    const float* gamma  = (const float*)d_in[3];
    const float* beta   = (const float*)d_in[4];
    const float* W2     = (const float*)d_in[5];
    const float* b2     = (const float*)d_in[6];
    const float* cent   = (const float*)d_in[7];
    float* out = (float*)d_out;

    cudaFuncSetAttribute(router_mma_kernel,
                         cudaFuncAttributeMaxDynamicSharedMemorySize, SMEM_TOTAL);

    zero_kernel<<<1, 64>>>(out, out_size);
    dim3 grid(NB / MT, NTASK);
    router_mma_kernel<<<grid, THREADS, SMEM_TOTAL>>>(
        t_feat, W1, b1, gamma, beta, W2, b2, cent, out, out_size);
    finalize_kernel<<<1, 64>>>(out, out_size);
}

// round 5
// speedup vs baseline: 7.7888x; 1.6574x over previous
#include <cuda_runtime.h>
#include <cuda_fp16.h>
#include <cstdint>
#include <math.h>

#define NTASK 64
#define NB    4096
#define TD    512
#define HD    256
#define VD    484
#define MT    128
#define KC    32            // halves per staged k-chunk
#define THREADS 512

// ---- smem layout (bytes) ----
// h: 128 rows x 264 halves (528B stride, ldmatrix conflict-free)
#define HSTR_B   528
#define SM_H     0
#define SM_H_SZ  (MT * HSTR_B)                  // 67584
// stage: A 128 rows x 80B = 10240 ; B 256 rows x 80B = 20480
#define STR_B    80
#define SM_STAGE SM_H_SZ
#define STAGE_BUF 30720
#define SM_PARB  (SM_STAGE + 2 * STAGE_BUF)     // 129024
// params (floats): b1s 256 | gms 256 | bts 256 | b2s 512 | cts 512 |
//                  rowSum 128 | rowSq 128 | vcA 128 | vvA 128 | red 32 = 2336
#define SMEM_TOTAL (SM_PARB + 2336 * 4)         // 138368

// fp16 scratch (device-global: allocation-free)
__device__ __half g_tfeat[NB * TD];
__device__ __half g_w1[NTASK * HD * TD];
__device__ __half g_w2[NTASK * VD * HD];

__device__ __forceinline__ uint32_t s2u(const void* p) {
    uint32_t a;
    asm("{ .reg .u64 t; cvta.to.shared.u64 t, %1; cvt.u32.u64 %0, t; }" : "=r"(a) : "l"(p));
    return a;
}
__device__ __forceinline__ void cp16(uint32_t dst, const void* src) {
    asm volatile("cp.async.cg.shared.global [%0], [%1], 16;" :: "r"(dst), "l"(src) : "memory");
}
__device__ __forceinline__ void cpcommit() { asm volatile("cp.async.commit_group;" ::: "memory"); }
__device__ __forceinline__ void cpwait1()  { asm volatile("cp.async.wait_group 1;" ::: "memory"); }
__device__ __forceinline__ void cpwait0()  { asm volatile("cp.async.wait_group 0;" ::: "memory"); }

__device__ __forceinline__ void ldsm4(uint32_t* r, uint32_t a) {
    asm volatile("ldmatrix.sync.aligned.m8n8.x4.shared.b16 {%0,%1,%2,%3}, [%4];"
                 : "=r"(r[0]), "=r"(r[1]), "=r"(r[2]), "=r"(r[3]) : "r"(a));
}
__device__ __forceinline__ void mma16(float* c, const uint32_t* a, uint32_t b0, uint32_t b1) {
    asm volatile(
        "mma.sync.aligned.m16n8k16.row.col.f32.f16.f16.f32 "
        "{%0,%1,%2,%3}, {%4,%5,%6,%7}, {%8,%9}, {%0,%1,%2,%3};"
        : "+f"(c[0]), "+f"(c[1]), "+f"(c[2]), "+f"(c[3])
        : "r"(a[0]), "r"(a[1]), "r"(a[2]), "r"(a[3]), "r"(b0), "r"(b1));
}
__device__ __forceinline__ void sth2(uint32_t a, __half2 v) {
    asm volatile("st.shared.b32 [%0], %1;" :: "r"(a), "r"(*(const uint32_t*)&v) : "memory");
}
__device__ __forceinline__ void stz4(uint32_t a) {
    asm volatile("st.shared.v4.b32 [%0], {%1,%1,%1,%1};" :: "r"(a), "r"(0u) : "memory");
}

// ---------------- convert + zero kernel ----------------
__global__ void convert_kernel(const float* __restrict__ t_feat,
                               const float* __restrict__ W1,
                               const float* __restrict__ W2,
                               float* __restrict__ out, int out_size)
{
    const int idx = blockIdx.x * blockDim.x + threadIdx.x;
    const int stride = gridDim.x * blockDim.x;
    if (idx < 65 && idx < out_size) out[idx] = 0.0f;
    for (int i = idx; i < NB * TD / 2; i += stride) {
        const float2 v = ((const float2*)t_feat)[i];
        ((__half2*)g_tfeat)[i] = __floats2half2_rn(v.x, v.y);
    }
    for (int i = idx; i < NTASK * HD * TD / 2; i += stride) {
        const float2 v = ((const float2*)W1)[i];
        ((__half2*)g_w1)[i] = __floats2half2_rn(v.x, v.y);
    }
    for (int i = idx; i < NTASK * VD * HD / 2; i += stride) {
        const float2 v = ((const float2*)W2)[i];
        ((__half2*)g_w2)[i] = __floats2half2_rn(v.x, v.y);
    }
}

// ---------------- main fused kernel ----------------
__global__ void __launch_bounds__(THREADS, 1)
router_h16_kernel(const float* __restrict__ b1,
                  const float* __restrict__ gamma,
                  const float* __restrict__ beta,
                  const float* __restrict__ b2,
                  const float* __restrict__ cent,
                  float* __restrict__ out, int out_size)
{
    extern __shared__ char smem[];
    const uint32_t sb = s2u(smem);
    const int tid  = threadIdx.x;
    const int lane = tid & 31;
    const int wid  = tid >> 5;
    const int wm   = wid & 3,  wn = wid >> 2;
    const int m0w  = wm * 32,  n0w = wn * 64;
    const int task = blockIdx.y;
    const int brow0 = blockIdx.x * MT;

    const __half* tA  = g_tfeat + (size_t)brow0 * TD;
    const __half* W1t = g_w1 + (size_t)task * HD * TD;
    const __half* W2t = g_w2 + (size_t)task * VD * HD;

    float* b1s    = (float*)(smem + SM_PARB);
    float* gms    = b1s + 256;
    float* bts    = gms + 256;
    float* b2s    = bts + 256;
    float* cts    = b2s + 512;
    float* rowSum = cts + 512;
    float* rowSq  = rowSum + 128;
    float* vcA    = rowSq + 128;
    float* vvA    = vcA + 128;
    float* red    = vvA + 128;

    // ldmatrix lane addressing
    const int arow   = lane & 15;
    const int acol16 = (lane >> 4) * 16;                  // bytes
    const int brow   = (lane & 7) | ((lane >> 4) << 3);
    const int bcol16 = ((lane >> 3) & 1) * 16;            // bytes

    // staging thread mapping
    const int sArow = tid >> 2, sAseg = tid & 3;

    // ---- prefetch GEMM1 chunk 0 ----
    {
        const uint32_t ab = sb + SM_STAGE;
        const uint32_t bb = ab + 10240;
        cp16(ab + (uint32_t)(sArow * STR_B + sAseg * 16), tA + (size_t)sArow * TD + sAseg * 8);
#pragma unroll
        for (int i = 0; i < 2; ++i) {
            const int s = tid + 512 * i, row = s >> 2, seg = s & 3;
            cp16(bb + (uint32_t)(row * STR_B + seg * 16), W1t + (size_t)row * TD + seg * 8);
        }
        cpcommit();
    }

    // ---- params + zeros ----
    if (tid < 256) {
        b1s[tid] = b1[task * HD + tid];
        gms[tid] = gamma[task * HD + tid];
        bts[tid] = beta[task * HD + tid];
    }
    {
        float bv = 0.f, cv = 0.f;
        if (tid < VD) { bv = b2[task * VD + tid]; cv = cent[task * VD + tid]; }
        b2s[tid] = bv; cts[tid] = cv;
        float ce = cv * cv;
#pragma unroll
        for (int o = 16; o > 0; o >>= 1) ce += __shfl_xor_sync(0xffffffffu, ce, o);
        if (lane == 0) red[wid] = ce;
    }
    if (tid < 128) { rowSum[tid] = 0.f; rowSq[tid] = 0.f; vcA[tid] = 0.f; vvA[tid] = 0.f; }

    float acc[2][8][4];
#pragma unroll
    for (int mb = 0; mb < 2; ++mb)
#pragma unroll
        for (int q = 0; q < 8; ++q)
#pragma unroll
            for (int c = 0; c < 4; ++c) acc[mb][q][c] = 0.f;

    // ================= GEMM1: K=512, 16 chunks of 32 halves =================
    for (int c = 0; c < 16; ++c) {
        if (c < 15) {
            const int kb = (c + 1) * KC;
            const uint32_t ab = sb + SM_STAGE + (uint32_t)((c + 1) & 1) * STAGE_BUF;
            const uint32_t bb = ab + 10240;
            cp16(ab + (uint32_t)(sArow * STR_B + sAseg * 16),
                 tA + (size_t)sArow * TD + kb + sAseg * 8);
#pragma unroll
            for (int i = 0; i < 2; ++i) {
                const int s = tid + 512 * i, row = s >> 2, seg = s & 3;
                cp16(bb + (uint32_t)(row * STR_B + seg * 16),
                     W1t + (size_t)row * TD + kb + seg * 8);
            }
            cpcommit();
            cpwait1();
        } else {
            cpwait0();
        }
        __syncthreads();
        const uint32_t ab = sb + SM_STAGE + (uint32_t)(c & 1) * STAGE_BUF;
        const uint32_t bb = ab + 10240;
#pragma unroll
        for (int ks = 0; ks < 2; ++ks) {
            uint32_t a[2][4];
#pragma unroll
            for (int mb = 0; mb < 2; ++mb)
                ldsm4(a[mb], ab + (uint32_t)((m0w + mb * 16 + arow) * STR_B + ks * 32 + acol16));
#pragma unroll
            for (int q = 0; q < 4; ++q) {
                uint32_t bq[4];
                ldsm4(bq, bb + (uint32_t)((n0w + q * 16 + brow) * STR_B + ks * 32 + bcol16));
#pragma unroll
                for (int mb = 0; mb < 2; ++mb) {
                    mma16(acc[mb][2 * q],     a[mb], bq[0], bq[1]);
                    mma16(acc[mb][2 * q + 1], a[mb], bq[2], bq[3]);
                }
            }
        }
        __syncthreads();
    }

    // ================= LayerNorm stats =================
    {
        float sums[4] = {0.f, 0.f, 0.f, 0.f}, sqs[4] = {0.f, 0.f, 0.f, 0.f};
#pragma unroll
        for (int mb = 0; mb < 2; ++mb)
#pragma unroll
            for (int q = 0; q < 8; ++q)
#pragma unroll
                for (int c = 0; c < 4; ++c) {
                    const int n = n0w + q * 8 + 2 * (lane & 3) + (c & 1);
                    const float x = acc[mb][q][c] + b1s[n];
                    acc[mb][q][c] = x;
                    const int key = (mb << 1) | (c >> 1);
                    sums[key] += x;
                    sqs[key]  = fmaf(x, x, sqs[key]);
                }
#pragma unroll
        for (int o = 1; o <= 2; o <<= 1)
#pragma unroll
            for (int k = 0; k < 4; ++k) {
                sums[k] += __shfl_xor_sync(0xffffffffu, sums[k], o);
                sqs[k]  += __shfl_xor_sync(0xffffffffu, sqs[k], o);
            }
        if ((lane & 3) == 0) {
#pragma unroll
            for (int k = 0; k < 4; ++k) {
                const int r = m0w + (k >> 1) * 16 + (k & 1) * 8 + (lane >> 2);
                atomicAdd(&rowSum[r], sums[k]);
                atomicAdd(&rowSq[r],  sqs[k]);
            }
        }
    }
    __syncthreads();

    // ================= normalize + exact GELU + store h (fp16) =================
#pragma unroll
    for (int mb = 0; mb < 2; ++mb)
#pragma unroll
        for (int cp = 0; cp < 2; ++cp) {
            const int r = m0w + mb * 16 + cp * 8 + (lane >> 2);
            const float mu   = rowSum[r] * (1.0f / HD);
            const float var  = rowSq[r] * (1.0f / HD) - mu * mu;
            const float rstd = rsqrtf(var + 1e-5f);
#pragma unroll
            for (int q = 0; q < 8; ++q) {
                const int n = n0w + q * 8 + 2 * (lane & 3);
                float y0 = (acc[mb][q][cp * 2]     - mu) * rstd * gms[n]     + bts[n];
                float y1 = (acc[mb][q][cp * 2 + 1] - mu) * rstd * gms[n + 1] + bts[n + 1];
                y0 = 0.5f * y0 * (1.0f + erff(y0 * 0.70710678118654752440f));
                y1 = 0.5f * y1 * (1.0f + erff(y1 * 0.70710678118654752440f));
                sth2(sb + SM_H + (uint32_t)(r * HSTR_B + n * 2), __floats2half2_rn(y0, y1));
            }
        }

    // ================= GEMM2 + cosine epilogue =================
    float vc4[4] = {0.f, 0.f, 0.f, 0.f}, vv4[4] = {0.f, 0.f, 0.f, 0.f};

    for (int half = 0; half < 2; ++half) {
#pragma unroll
        for (int mb = 0; mb < 2; ++mb)
#pragma unroll
            for (int q = 0; q < 8; ++q)
#pragma unroll
                for (int c = 0; c < 4; ++c) acc[mb][q][c] = 0.f;

        {   // prefetch chunk 0
            const uint32_t bb = sb + SM_STAGE + 10240;
#pragma unroll
            for (int i = 0; i < 2; ++i) {
                const int s = tid + 512 * i, row = s >> 2, seg = s & 3;
                const int n = half * 256 + row;
                const uint32_t dst = bb + (uint32_t)(row * STR_B + seg * 16);
                if (n < VD) cp16(dst, W2t + (size_t)n * HD + seg * 8);
                else        stz4(dst);
            }
            cpcommit();
        }
        for (int c = 0; c < 8; ++c) {
            if (c < 7) {
                const int kb = (c + 1) * KC;
                const uint32_t bb = sb + SM_STAGE + (uint32_t)((c + 1) & 1) * STAGE_BUF + 10240;
#pragma unroll
                for (int i = 0; i < 2; ++i) {
                    const int s = tid + 512 * i, row = s >> 2, seg = s & 3;
                    const int n = half * 256 + row;
                    const uint32_t dst = bb + (uint32_t)(row * STR_B + seg * 16);
                    if (n < VD) cp16(dst, W2t + (size_t)n * HD + kb + seg * 8);
                    else        stz4(dst);
                }
                cpcommit();
                cpwait1();
            } else {
                cpwait0();
            }
            __syncthreads();
            const uint32_t bb = sb + SM_STAGE + (uint32_t)(c & 1) * STAGE_BUF + 10240;
            const int kbB = c * KC * 2;  // byte offset into h rows
#pragma unroll
            for (int ks = 0; ks < 2; ++ks) {
                uint32_t a[2][4];
#pragma unroll
                for (int mb = 0; mb < 2; ++mb)
                    ldsm4(a[mb], sb + SM_H +
                          (uint32_t)((m0w + mb * 16 + arow) * HSTR_B + kbB + ks * 32 + acol16));
#pragma unroll
                for (int q = 0; q < 4; ++q) {
                    uint32_t bq[4];
                    ldsm4(bq, bb + (uint32_t)((n0w + q * 16 + brow) * STR_B + ks * 32 + bcol16));
#pragma unroll
                    for (int mb = 0; mb < 2; ++mb) {
                        mma16(acc[mb][2 * q],     a[mb], bq[0], bq[1]);
                        mma16(acc[mb][2 * q + 1], a[mb], bq[2], bq[3]);
                    }
                }
            }
            __syncthreads();
        }
        // fold b2 + centroid
#pragma unroll
        for (int mb = 0; mb < 2; ++mb)
#pragma unroll
            for (int q = 0; q < 8; ++q)
#pragma unroll
                for (int c = 0; c < 4; ++c) {
                    const int n = half * 256 + n0w + q * 8 + 2 * (lane & 3) + (c & 1);
                    const float v = acc[mb][q][c] + b2s[n];
                    const int key = (mb << 1) | (c >> 1);
                    vc4[key] = fmaf(v, cts[n], vc4[key]);
                    vv4[key] = fmaf(v, v,     vv4[key]);
                }
    }

#pragma unroll
    for (int o = 1; o <= 2; o <<= 1)
#pragma unroll
        for (int k = 0; k < 4; ++k) {
            vc4[k] += __shfl_xor_sync(0xffffffffu, vc4[k], o);
            vv4[k] += __shfl_xor_sync(0xffffffffu, vv4[k], o);
        }
    if ((lane & 3) == 0) {
#pragma unroll
        for (int k = 0; k < 4; ++k) {
            const int r = m0w + (k >> 1) * 16 + (k & 1) * 8 + (lane >> 2);
            atomicAdd(&vcA[r], vc4[k]);
            atomicAdd(&vvA[r], vv4[k]);
        }
    }
    __syncthreads();

    float dist = 0.f;
    if (tid < 128) {
        float cn2 = 0.f;
#pragma unroll
        for (int i = 0; i < 16; ++i) cn2 += red[i];
        const float cn = fmaxf(sqrtf(cn2), 1e-8f);
        const float vn = fmaxf(sqrtf(vvA[tid]), 1e-8f);
        dist = 1.0f - vcA[tid] / (vn * cn);
    }
#pragma unroll
    for (int o = 16; o > 0; o >>= 1) dist += __shfl_xor_sync(0xffffffffu, dist, o);
    if (tid < 128 && lane == 0) red[16 + wid] = dist;
    __syncthreads();
    if (tid == 0 && task < out_size) {
        atomicAdd(&out[task], red[16] + red[17] + red[18] + red[19]);
    }
}

__global__ void finalize_kernel(float* __restrict__ out, int out_size) {
    __shared__ float d[64];
    const int t = threadIdx.x;
    float v = 0.0f;
    if (t < out_size) {
        v = out[t] * (1.0f / (float)NB);
        out[t] = v;
    }
    d[t] = v;
    __syncthreads();
    if (t == 0) {
        int best = 0;
        float bv = d[0];
#pragma unroll 1
        for (int i = 1; i < 64; ++i)
            if (d[i] < bv) { bv = d[i]; best = i; }
        if (out_size > 64) out[64] = (float)best;
    }
}

extern "C" void kernel_launch(void* const* d_in, const int* in_sizes, int n_in,
                              void* d_out, int out_size) {
    const float* t_feat = (const float*)d_in[0];
    const float* W1     = (const float*)d_in[1];
    const float* b1     = (const float*)d_in[2];
    const float* gamma  = (const float*)d_in[3];
    const float* beta   = (const float*)d_in[4];
    const float* W2     = (const float*)d_in[5];
    const float* b2     = (const float*)d_in[6];
    const float* cent   = (const float*)d_in[7];
    float* out = (float*)d_out;

    cudaFuncSetAttribute(router_h16_kernel,
                         cudaFuncAttributeMaxDynamicSharedMemorySize, SMEM_TOTAL);

    convert_kernel<<<2048, 256>>>(t_feat, W1, W2, out, out_size);
    dim3 grid(NB / MT, NTASK);
    router_h16_kernel<<<grid, THREADS, SMEM_TOTAL>>>(
        b1, gamma, beta, b2, cent, out, out_size);
    finalize_kernel<<<1, 64>>>(out, out_size);
}

// round 6
// speedup vs baseline: 7.8477x; 1.0076x over previous
#include <cuda_runtime.h>
#include <cuda_fp16.h>
#include <cstdint>
#include <math.h>

#define NTASK 64
#define NB    4096
#define TD    512
#define HD    256
#define VD    484
#define MT    128
#define KC    32            // halves per staged k-chunk
#define THREADS 512

// ---- smem layout (bytes) ----
#define HSTR_B   528
#define SM_H     0
#define SM_H_SZ  (MT * HSTR_B)                  // 67584
#define STR_B    80
#define SM_STAGE SM_H_SZ
#define STAGE_BUF 30720                          // A 10240 + B 20480
#define SM_PARB  (SM_STAGE + 3 * STAGE_BUF)     // 159744
// params (floats): b1s 256 | gms 256 | bts 256 | b2s 512 | cts 512 |
//                  rowSum 128 | rowSq 128 | vcA 128 | vvA 128 | red 32 | flag 1
#define SMEM_TOTAL (SM_PARB + 2340 * 4)         // 169104

__device__ __half g_tfeat[NB * TD];
__device__ __half g_w1[NTASK * HD * TD];
__device__ __half g_w2[NTASK * VD * HD];
__device__ unsigned int g_count;

__device__ __forceinline__ uint32_t s2u(const void* p) {
    uint32_t a;
    asm("{ .reg .u64 t; cvta.to.shared.u64 t, %1; cvt.u32.u64 %0, t; }" : "=r"(a) : "l"(p));
    return a;
}
__device__ __forceinline__ void cp16(uint32_t dst, const void* src) {
    asm volatile("cp.async.cg.shared.global [%0], [%1], 16;" :: "r"(dst), "l"(src) : "memory");
}
__device__ __forceinline__ void cpcommit() { asm volatile("cp.async.commit_group;" ::: "memory"); }
__device__ __forceinline__ void cpwait1()  { asm volatile("cp.async.wait_group 1;" ::: "memory"); }
__device__ __forceinline__ void cpwait0()  { asm volatile("cp.async.wait_group 0;" ::: "memory"); }

__device__ __forceinline__ void ldsm4(uint32_t* r, uint32_t a) {
    asm volatile("ldmatrix.sync.aligned.m8n8.x4.shared.b16 {%0,%1,%2,%3}, [%4];"
                 : "=r"(r[0]), "=r"(r[1]), "=r"(r[2]), "=r"(r[3]) : "r"(a));
}
__device__ __forceinline__ void mma16(float* c, const uint32_t* a, uint32_t b0, uint32_t b1) {
    asm volatile(
        "mma.sync.aligned.m16n8k16.row.col.f32.f16.f16.f32 "
        "{%0,%1,%2,%3}, {%4,%5,%6,%7}, {%8,%9}, {%0,%1,%2,%3};"
        : "+f"(c[0]), "+f"(c[1]), "+f"(c[2]), "+f"(c[3])
        : "r"(a[0]), "r"(a[1]), "r"(a[2]), "r"(a[3]), "r"(b0), "r"(b1));
}
__device__ __forceinline__ void sth2(uint32_t a, __half2 v) {
    asm volatile("st.shared.b32 [%0], %1;" :: "r"(a), "r"(*(const uint32_t*)&v) : "memory");
}
__device__ __forceinline__ void stz4(uint32_t a) {
    asm volatile("st.shared.v4.b32 [%0], {%1,%1,%1,%1};" :: "r"(a), "r"(0u) : "memory");
}

// ---------------- convert + zero kernel ----------------
__global__ void convert_kernel(const float* __restrict__ t_feat,
                               const float* __restrict__ W1,
                               const float* __restrict__ W2,
                               float* __restrict__ out, int out_size)
{
    const int idx = blockIdx.x * blockDim.x + threadIdx.x;
    const int stride = gridDim.x * blockDim.x;
    if (idx < 65 && idx < out_size) out[idx] = 0.0f;
    for (int i = idx; i < NB * TD / 2; i += stride) {
        const float2 v = ((const float2*)t_feat)[i];
        ((__half2*)g_tfeat)[i] = __floats2half2_rn(v.x, v.y);
    }
    for (int i = idx; i < NTASK * HD * TD / 2; i += stride) {
        const float2 v = ((const float2*)W1)[i];
        ((__half2*)g_w1)[i] = __floats2half2_rn(v.x, v.y);
    }
    for (int i = idx; i < NTASK * VD * HD / 2; i += stride) {
        const float2 v = ((const float2*)W2)[i];
        ((__half2*)g_w2)[i] = __floats2half2_rn(v.x, v.y);
    }
}

// ---------------- main fused kernel ----------------
__global__ void __launch_bounds__(THREADS, 1)
router_h16_kernel(const float* __restrict__ b1,
                  const float* __restrict__ gamma,
                  const float* __restrict__ beta,
                  const float* __restrict__ b2,
                  const float* __restrict__ cent,
                  float* __restrict__ out, int out_size)
{
    extern __shared__ char smem[];
    const uint32_t sb = s2u(smem);
    const int tid  = threadIdx.x;
    const int lane = tid & 31;
    const int wid  = tid >> 5;
    const int wm   = wid & 3,  wn = wid >> 2;
    const int m0w  = wm * 32,  n0w = wn * 64;
    const int task = blockIdx.y;
    const int brow0 = blockIdx.x * MT;

    const __half* tA  = g_tfeat + (size_t)brow0 * TD;
    const __half* W1t = g_w1 + (size_t)task * HD * TD;
    const __half* W2t = g_w2 + (size_t)task * VD * HD;

    float* b1s    = (float*)(smem + SM_PARB);
    float* gms    = b1s + 256;
    float* bts    = gms + 256;
    float* b2s    = bts + 256;
    float* cts    = b2s + 512;
    float* rowSum = cts + 512;
    float* rowSq  = rowSum + 128;
    float* vcA    = rowSq + 128;
    float* vvA    = vcA + 128;
    float* red    = vvA + 128;       // 32
    int*   flag   = (int*)(red + 32);

    // ldmatrix lane addressing
    const int arow   = lane & 15;
    const int acol16 = (lane >> 4) * 16;
    const int brow   = (lane & 7) | ((lane >> 4) << 3);
    const int bcol16 = ((lane >> 3) & 1) * 16;

    // staging thread mapping
    const int sArow = tid >> 2, sAseg = tid & 3;

    // ---- prologue: issue GEMM1 chunks 0 and 1 ----
#pragma unroll
    for (int pc = 0; pc < 2; ++pc) {
        const uint32_t ab = sb + SM_STAGE + (uint32_t)pc * STAGE_BUF;
        const uint32_t bb = ab + 10240;
        const int kb = pc * KC;
        cp16(ab + (uint32_t)(sArow * STR_B + sAseg * 16),
             tA + (size_t)sArow * TD + kb + sAseg * 8);
#pragma unroll
        for (int i = 0; i < 2; ++i) {
            const int s = tid + 512 * i, row = s >> 2, seg = s & 3;
            cp16(bb + (uint32_t)(row * STR_B + seg * 16),
                 W1t + (size_t)row * TD + kb + seg * 8);
        }
        cpcommit();
    }

    // ---- params + zeros (overlaps the in-flight cp.async) ----
    if (tid < 256) {
        b1s[tid] = b1[task * HD + tid];
        gms[tid] = gamma[task * HD + tid];
        bts[tid] = beta[task * HD + tid];
    }
    {
        float bv = 0.f, cv = 0.f;
        if (tid < VD) { bv = b2[task * VD + tid]; cv = cent[task * VD + tid]; }
        b2s[tid] = bv; cts[tid] = cv;
        float ce = cv * cv;
#pragma unroll
        for (int o = 16; o > 0; o >>= 1) ce += __shfl_xor_sync(0xffffffffu, ce, o);
        if (lane == 0) red[wid] = ce;
    }
    if (tid < 128) { rowSum[tid] = 0.f; rowSq[tid] = 0.f; vcA[tid] = 0.f; vvA[tid] = 0.f; }

    float acc[2][8][4];
#pragma unroll
    for (int mb = 0; mb < 2; ++mb)
#pragma unroll
        for (int q = 0; q < 8; ++q)
#pragma unroll
            for (int c = 0; c < 4; ++c) acc[mb][q][c] = 0.f;

    // ================= GEMM1: 16 chunks, 3-stage ring, 1 sync/chunk =============
    for (int c = 0; c < 16; ++c) {
        if (c < 15) cpwait1(); else cpwait0();
        __syncthreads();
        if (c + 2 < 16) {
            const int kb = (c + 2) * KC;
            const uint32_t ab = sb + SM_STAGE + (uint32_t)((c + 2) % 3) * STAGE_BUF;
            const uint32_t bb = ab + 10240;
            cp16(ab + (uint32_t)(sArow * STR_B + sAseg * 16),
                 tA + (size_t)sArow * TD + kb + sAseg * 8);
#pragma unroll
            for (int i = 0; i < 2; ++i) {
                const int s = tid + 512 * i, row = s >> 2, seg = s & 3;
                cp16(bb + (uint32_t)(row * STR_B + seg * 16),
                     W1t + (size_t)row * TD + kb + seg * 8);
            }
            cpcommit();
        }
        const uint32_t ab = sb + SM_STAGE + (uint32_t)(c % 3) * STAGE_BUF;
        const uint32_t bb = ab + 10240;
#pragma unroll
        for (int ks = 0; ks < 2; ++ks) {
            uint32_t a[2][4];
#pragma unroll
            for (int mb = 0; mb < 2; ++mb)
                ldsm4(a[mb], ab + (uint32_t)((m0w + mb * 16 + arow) * STR_B + ks * 32 + acol16));
#pragma unroll
            for (int q = 0; q < 4; ++q) {
                uint32_t bq[4];
                ldsm4(bq, bb + (uint32_t)((n0w + q * 16 + brow) * STR_B + ks * 32 + bcol16));
#pragma unroll
                for (int mb = 0; mb < 2; ++mb) {
                    mma16(acc[mb][2 * q],     a[mb], bq[0], bq[1]);
                    mma16(acc[mb][2 * q + 1], a[mb], bq[2], bq[3]);
                }
            }
        }
    }

    // ================= LayerNorm stats =================
    {
        float sums[4] = {0.f, 0.f, 0.f, 0.f}, sqs[4] = {0.f, 0.f, 0.f, 0.f};
#pragma unroll
        for (int mb = 0; mb < 2; ++mb)
#pragma unroll
            for (int q = 0; q < 8; ++q)
#pragma unroll
                for (int c = 0; c < 4; ++c) {
                    const int n = n0w + q * 8 + 2 * (lane & 3) + (c & 1);
                    const float x = acc[mb][q][c] + b1s[n];
                    acc[mb][q][c] = x;
                    const int key = (mb << 1) | (c >> 1);
                    sums[key] += x;
                    sqs[key]  = fmaf(x, x, sqs[key]);
                }
#pragma unroll
        for (int o = 1; o <= 2; o <<= 1)
#pragma unroll
            for (int k = 0; k < 4; ++k) {
                sums[k] += __shfl_xor_sync(0xffffffffu, sums[k], o);
                sqs[k]  += __shfl_xor_sync(0xffffffffu, sqs[k], o);
            }
        if ((lane & 3) == 0) {
#pragma unroll
            for (int k = 0; k < 4; ++k) {
                const int r = m0w + (k >> 1) * 16 + (k & 1) * 8 + (lane >> 2);
                atomicAdd(&rowSum[r], sums[k]);
                atomicAdd(&rowSq[r],  sqs[k]);
            }
        }
    }
    __syncthreads();   // rowSum/rowSq complete; all GEMM1 reads of ring done

    // ---- issue GEMM2 chunks 0,1 NOW (overlap with LN/GELU math below) ----
#pragma unroll
    for (int pg = 0; pg < 2; ++pg) {
        const uint32_t bb = sb + SM_STAGE + (uint32_t)pg * STAGE_BUF + 10240;
        const int kb = pg * KC;
#pragma unroll
        for (int i = 0; i < 2; ++i) {
            const int s = tid + 512 * i, row = s >> 2, seg = s & 3;
            const uint32_t dst = bb + (uint32_t)(row * STR_B + seg * 16);
            if (row < VD) cp16(dst, W2t + (size_t)row * HD + kb + seg * 8);
            else          stz4(dst);
        }
        cpcommit();
    }

    // ================= normalize + exact GELU + store h (fp16) =================
#pragma unroll
    for (int mb = 0; mb < 2; ++mb)
#pragma unroll
        for (int cp = 0; cp < 2; ++cp) {
            const int r = m0w + mb * 16 + cp * 8 + (lane >> 2);
            const float mu   = rowSum[r] * (1.0f / HD);
            const float var  = rowSq[r] * (1.0f / HD) - mu * mu;
            const float rstd = rsqrtf(var + 1e-5f);
#pragma unroll
            for (int q = 0; q < 8; ++q) {
                const int n = n0w + q * 8 + 2 * (lane & 3);
                float y0 = (acc[mb][q][cp * 2]     - mu) * rstd * gms[n]     + bts[n];
                float y1 = (acc[mb][q][cp * 2 + 1] - mu) * rstd * gms[n + 1] + bts[n + 1];
                y0 = 0.5f * y0 * (1.0f + erff(y0 * 0.70710678118654752440f));
                y1 = 0.5f * y1 * (1.0f + erff(y1 * 0.70710678118654752440f));
                sth2(sb + SM_H + (uint32_t)(r * HSTR_B + n * 2), __floats2half2_rn(y0, y1));
            }
        }

    // ================= GEMM2 (16 global chunks = 2 halves x 8) + cosine ==========
    float vc4[4] = {0.f, 0.f, 0.f, 0.f}, vv4[4] = {0.f, 0.f, 0.f, 0.f};

    for (int gc = 0; gc < 16; ++gc) {
        const int half = gc >> 3, kc8 = gc & 7;
        if (gc == 8 || gc == 0) {
            // new accumulator block per half
            if (gc == 8) {
                // fold half 0 results before reusing acc
#pragma unroll
                for (int mb = 0; mb < 2; ++mb)
#pragma unroll
                    for (int q = 0; q < 8; ++q)
#pragma unroll
                        for (int c = 0; c < 4; ++c) {
                            const int n = n0w + q * 8 + 2 * (lane & 3) + (c & 1);
                            const float v = acc[mb][q][c] + b2s[n];
                            const int key = (mb << 1) | (c >> 1);
                            vc4[key] = fmaf(v, cts[n], vc4[key]);
                            vv4[key] = fmaf(v, v,     vv4[key]);
                        }
            }
#pragma unroll
            for (int mb = 0; mb < 2; ++mb)
#pragma unroll
                for (int q = 0; q < 8; ++q)
#pragma unroll
                    for (int c = 0; c < 4; ++c) acc[mb][q][c] = 0.f;
        }
        if (gc < 14) cpwait1(); else cpwait0();
        __syncthreads();
        if (gc + 2 < 16) {
            const int nh = (gc + 2) >> 3, nk = (gc + 2) & 7;
            const uint32_t bb = sb + SM_STAGE + (uint32_t)((gc + 2) % 3) * STAGE_BUF + 10240;
            const int kb = nk * KC;
#pragma unroll
            for (int i = 0; i < 2; ++i) {
                const int s = tid + 512 * i, row = s >> 2, seg = s & 3;
                const int n = nh * 256 + row;
                const uint32_t dst = bb + (uint32_t)(row * STR_B + seg * 16);
                if (n < VD) cp16(dst, W2t + (size_t)n * HD + kb + seg * 8);
                else        stz4(dst);
            }
            cpcommit();
        }
        const uint32_t bb = sb + SM_STAGE + (uint32_t)(gc % 3) * STAGE_BUF + 10240;
        const int kbB = kc8 * KC * 2;
#pragma unroll
        for (int ks = 0; ks < 2; ++ks) {
            uint32_t a[2][4];
#pragma unroll
            for (int mb = 0; mb < 2; ++mb)
                ldsm4(a[mb], sb + SM_H +
                      (uint32_t)((m0w + mb * 16 + arow) * HSTR_B + kbB + ks * 32 + acol16));
#pragma unroll
            for (int q = 0; q < 4; ++q) {
                uint32_t bq[4];
                ldsm4(bq, bb + (uint32_t)((n0w + q * 16 + brow) * STR_B + ks * 32 + bcol16));
#pragma unroll
                for (int mb = 0; mb < 2; ++mb) {
                    mma16(acc[mb][2 * q],     a[mb], bq[0], bq[1]);
                    mma16(acc[mb][2 * q + 1], a[mb], bq[2], bq[3]);
                }
            }
        }
    }
    // fold half 1
#pragma unroll
    for (int mb = 0; mb < 2; ++mb)
#pragma unroll
        for (int q = 0; q < 8; ++q)
#pragma unroll
            for (int c = 0; c < 4; ++c) {
                const int n = 256 + n0w + q * 8 + 2 * (lane & 3) + (c & 1);
                const float v = acc[mb][q][c] + b2s[n];
                const int key = (mb << 1) | (c >> 1);
                vc4[key] = fmaf(v, cts[n], vc4[key]);
                vv4[key] = fmaf(v, v,     vv4[key]);
            }

#pragma unroll
    for (int o = 1; o <= 2; o <<= 1)
#pragma unroll
        for (int k = 0; k < 4; ++k) {
            vc4[k] += __shfl_xor_sync(0xffffffffu, vc4[k], o);
            vv4[k] += __shfl_xor_sync(0xffffffffu, vv4[k], o);
        }
    if ((lane & 3) == 0) {
#pragma unroll
        for (int k = 0; k < 4; ++k) {
            const int r = m0w + (k >> 1) * 16 + (k & 1) * 8 + (lane >> 2);
            atomicAdd(&vcA[r], vc4[k]);
            atomicAdd(&vvA[r], vv4[k]);
        }
    }
    __syncthreads();

    float dist = 0.f;
    if (tid < 128) {
        float cn2 = 0.f;
#pragma unroll
        for (int i = 0; i < 16; ++i) cn2 += red[i];
        const float cn = fmaxf(sqrtf(cn2), 1e-8f);
        const float vn = fmaxf(sqrtf(vvA[tid]), 1e-8f);
        dist = 1.0f - vcA[tid] / (vn * cn);
    }
#pragma unroll
    for (int o = 16; o > 0; o >>= 1) dist += __shfl_xor_sync(0xffffffffu, dist, o);
    if (tid < 128 && lane == 0) red[16 + wid] = dist;
    __syncthreads();
    if (tid == 0) {
        if (task < out_size)
            atomicAdd(&out[task], red[16] + red[17] + red[18] + red[19]);
        __threadfence();
        const unsigned int old = atomicAdd(&g_count, 1u);
        *flag = (old == (unsigned)(NTASK * (NB / MT) - 1)) ? 1 : 0;
    }
    __syncthreads();

    // ---- last CTA finalizes: scale + argmin ----
    if (*flag) {
        __threadfence();
        float v = 0.0f;
        if (tid < NTASK && tid < out_size) {
            v = out[tid] * (1.0f / (float)NB);
            out[tid] = v;
        }
        if (tid < NTASK) b1s[tid] = v;   // reuse as scratch
        __syncthreads();
        if (tid == 0) {
            int best = 0;
            float bv = b1s[0];
#pragma unroll 1
            for (int i = 1; i < NTASK; ++i)
                if (b1s[i] < bv) { bv = b1s[i]; best = i; }
            if (out_size > 64) out[64] = (float)best;
            g_count = 0u;
        }
    }
}

extern "C" void kernel_launch(void* const* d_in, const int* in_sizes, int n_in,
                              void* d_out, int out_size) {
    const float* t_feat = (const float*)d_in[0];
    const float* W1     = (const float*)d_in[1];
    const float* b1     = (const float*)d_in[2];
    const float* gamma  = (const float*)d_in[3];
    const float* beta   = (const float*)d_in[4];
    const float* W2     = (const float*)d_in[5];
    const float* b2     = (const float*)d_in[6];
    const float* cent   = (const float*)d_in[7];
    float* out = (float*)d_out;

    cudaFuncSetAttribute(router_h16_kernel,
                         cudaFuncAttributeMaxDynamicSharedMemorySize, SMEM_TOTAL);

    convert_kernel<<<2048, 256>>>(t_feat, W1, W2, out, out_size);
    dim3 grid(NB / MT, NTASK);
    router_h16_kernel<<<grid, THREADS, SMEM_TOTAL>>>(
        b1, gamma, beta, b2, cent, out, out_size);
}

// round 9
// speedup vs baseline: 8.0634x; 1.0275x over previous
#include <cuda_runtime.h>
#include <cuda_fp16.h>
#include <cstdint>
#include <math.h>

#define NTASK 64
#define NB    4096
#define TD    512
#define HD    256
#define VD    484
#define MT    128
#define KC    32            // halves per staged k-chunk
#define THREADS 512

// ---- smem layout (bytes) ----
#define HSTR_B   528
#define SM_H     0
#define SM_H_SZ  (MT * HSTR_B)                  // 67584
#define STR_B    80
#define SM_STAGE SM_H_SZ
#define STAGE_BUF 30720                          // A 10240 + B 20480
#define SM_PARB  (SM_STAGE + 3 * STAGE_BUF)     // 159744
#define SMEM_TOTAL (SM_PARB + 2340 * 4)         // 169104

__device__ __half g_tfeat[NB * TD];
__device__ __half g_w1[NTASK * HD * TD];
__device__ __half g_w2[NTASK * VD * HD];
__device__ unsigned int g_count;

__device__ __forceinline__ uint32_t s2u(const void* p) {
    uint32_t a;
    asm("{ .reg .u64 t; cvta.to.shared.u64 t, %1; cvt.u32.u64 %0, t; }" : "=r"(a) : "l"(p));
    return a;
}
__device__ __forceinline__ void cp16(uint32_t dst, const void* src) {
    asm volatile("cp.async.cg.shared.global [%0], [%1], 16;" :: "r"(dst), "l"(src) : "memory");
}
__device__ __forceinline__ void cpcommit() { asm volatile("cp.async.commit_group;" ::: "memory"); }
__device__ __forceinline__ void cpwait1()  { asm volatile("cp.async.wait_group 1;" ::: "memory"); }
__device__ __forceinline__ void cpwait0()  { asm volatile("cp.async.wait_group 0;" ::: "memory"); }

__device__ __forceinline__ void ldsm4(uint32_t* r, uint32_t a) {
    asm volatile("ldmatrix.sync.aligned.m8n8.x4.shared.b16 {%0,%1,%2,%3}, [%4];"
                 : "=r"(r[0]), "=r"(r[1]), "=r"(r[2]), "=r"(r[3]) : "r"(a));
}
__device__ __forceinline__ void mma16(float* c, const uint32_t* a, uint32_t b0, uint32_t b1) {
    asm volatile(
        "mma.sync.aligned.m16n8k16.row.col.f32.f16.f16.f32 "
        "{%0,%1,%2,%3}, {%4,%5,%6,%7}, {%8,%9}, {%0,%1,%2,%3};"
        : "+f"(c[0]), "+f"(c[1]), "+f"(c[2]), "+f"(c[3])
        : "r"(a[0]), "r"(a[1]), "r"(a[2]), "r"(a[3]), "r"(b0), "r"(b1));
}
__device__ __forceinline__ void sth2(uint32_t a, __half2 v) {
    asm volatile("st.shared.b32 [%0], %1;" :: "r"(a), "r"(*(const uint32_t*)&v) : "memory");
}
__device__ __forceinline__ void stz4(uint32_t a) {
    asm volatile("st.shared.v4.b32 [%0], {%1,%1,%1,%1};" :: "r"(a), "r"(0u) : "memory");
}

// ---------------- convert + zero kernel ----------------
__global__ void convert_kernel(const float* __restrict__ t_feat,
                               const float* __restrict__ W1,
                               const float* __restrict__ W2,
                               float* __restrict__ out, int out_size)
{
    const int idx = blockIdx.x * blockDim.x + threadIdx.x;
    const int stride = gridDim.x * blockDim.x;
    if (idx < 65 && idx < out_size) out[idx] = 0.0f;
    for (int i = idx; i < NB * TD / 2; i += stride) {
        const float2 v = ((const float2*)t_feat)[i];
        ((__half2*)g_tfeat)[i] = __floats2half2_rn(v.x, v.y);
    }
    for (int i = idx; i < NTASK * HD * TD / 2; i += stride) {
        const float2 v = ((const float2*)W1)[i];
        ((__half2*)g_w1)[i] = __floats2half2_rn(v.x, v.y);
    }
    for (int i = idx; i < NTASK * VD * HD / 2; i += stride) {
        const float2 v = ((const float2*)W2)[i];
        ((__half2*)g_w2)[i] = __floats2half2_rn(v.x, v.y);
    }
}

// ---------------- main fused kernel ----------------
__global__ void __launch_bounds__(THREADS, 1)
router_h16_kernel(const float* __restrict__ b1,
                  const float* __restrict__ gamma,
                  const float* __restrict__ beta,
                  const float* __restrict__ b2,
                  const float* __restrict__ cent,
                  float* __restrict__ out, int out_size)
{
    extern __shared__ char smem[];
    const uint32_t sb = s2u(smem);
    const int tid  = threadIdx.x;
    const int lane = tid & 31;
    const int wid  = tid >> 5;
    const int wm   = wid & 3,  wn = wid >> 2;
    const int m0w  = wm * 32,  n0w = wn * 64;
    const int task = blockIdx.y;
    const int brow0 = blockIdx.x * MT;

    const __half* tA  = g_tfeat + (size_t)brow0 * TD;
    const __half* W1t = g_w1 + (size_t)task * HD * TD;
    const __half* W2t = g_w2 + (size_t)task * VD * HD;

    float* b1s    = (float*)(smem + SM_PARB);
    float* gms    = b1s + 256;
    float* bts    = gms + 256;
    float* b2s    = bts + 256;
    float* cts    = b2s + 512;
    float* rowSum = cts + 512;
    float* rowSq  = rowSum + 128;
    float* vcA    = rowSq + 128;
    float* vvA    = vcA + 128;
    float* red    = vvA + 128;       // 32
    int*   flag   = (int*)(red + 32);

    // ldmatrix lane addressing (byte offsets within a tile)
    const int arow   = lane & 15;
    const int acol16 = (lane >> 4) * 16;
    const int brow   = (lane & 7) | ((lane >> 4) << 3);
    const int bcol16 = ((lane >> 3) & 1) * 16;
    // per-warp relative offsets
    const uint32_t aOffW = (uint32_t)((m0w + arow) * STR_B + acol16);        // stage A
    const uint32_t bOffW = (uint32_t)((n0w + brow) * STR_B + bcol16);       // stage B
    const uint32_t hOffW = (uint32_t)((m0w + arow) * HSTR_B + acol16);      // h tile A

    // staging thread mapping
    const int sArow = tid >> 2, sAseg = tid & 3;

    // ---- prologue: issue GEMM1 chunks 0 and 1 ----
#pragma unroll
    for (int pc = 0; pc < 2; ++pc) {
        const uint32_t ab = sb + SM_STAGE + (uint32_t)pc * STAGE_BUF;
        const uint32_t bb = ab + 10240;
        const int kb = pc * KC;
        cp16(ab + (uint32_t)(sArow * STR_B + sAseg * 16),
             tA + (size_t)sArow * TD + kb + sAseg * 8);
#pragma unroll
        for (int i = 0; i < 2; ++i) {
            const int s = tid + 512 * i, row = s >> 2, seg = s & 3;
            cp16(bb + (uint32_t)(row * STR_B + seg * 16),
                 W1t + (size_t)row * TD + kb + seg * 8);
        }
        cpcommit();
    }

    // ---- params + zeros (overlaps the in-flight cp.async) ----
    if (tid < 256) {
        b1s[tid] = b1[task * HD + tid];
        gms[tid] = gamma[task * HD + tid];
        bts[tid] = beta[task * HD + tid];
    }
    {
        float bv = 0.f, cv = 0.f;
        if (tid < VD) { bv = b2[task * VD + tid]; cv = cent[task * VD + tid]; }
        b2s[tid] = bv; cts[tid] = cv;
        float ce = cv * cv;
#pragma unroll
        for (int o = 16; o > 0; o >>= 1) ce += __shfl_xor_sync(0xffffffffu, ce, o);
        if (lane == 0) red[wid] = ce;
    }
    if (tid < 128) { rowSum[tid] = 0.f; rowSq[tid] = 0.f; vcA[tid] = 0.f; vvA[tid] = 0.f; }

    float acc[2][8][4];
#pragma unroll
    for (int mb = 0; mb < 2; ++mb)
#pragma unroll
        for (int q = 0; q < 8; ++q)
#pragma unroll
            for (int c = 0; c < 4; ++c) acc[mb][q][c] = 0.f;

    // ================= GEMM1: 16 chunks, 3-stage ring, pipelined fragments ========
    for (int c = 0; c < 16; ++c) {
        if (c < 15) cpwait1(); else cpwait0();
        __syncthreads();
        if (c + 2 < 16) {
            const int kb = (c + 2) * KC;
            const uint32_t ab = sb + SM_STAGE + (uint32_t)((c + 2) % 3) * STAGE_BUF;
            const uint32_t bb = ab + 10240;
            cp16(ab + (uint32_t)(sArow * STR_B + sAseg * 16),
                 tA + (size_t)sArow * TD + kb + sAseg * 8);
#pragma unroll
            for (int i = 0; i < 2; ++i) {
                const int s = tid + 512 * i, row = s >> 2, seg = s & 3;
                cp16(bb + (uint32_t)(row * STR_B + seg * 16),
                     W1t + (size_t)row * TD + kb + seg * 8);
            }
            cpcommit();
        }
        const uint32_t ab = sb + SM_STAGE + (uint32_t)(c % 3) * STAGE_BUF;
        const uint32_t bb = ab + 10240;
        const uint32_t aA = ab + aOffW;
        const uint32_t bA = bb + bOffW;

        uint32_t afr[2][2][4];   // [ks][mb]
        uint32_t bfr[2][4];      // double buffer
        ldsm4(afr[0][0], aA);
        ldsm4(afr[0][1], aA + 16 * STR_B);
        ldsm4(bfr[0], bA);
#pragma unroll
        for (int s8 = 0; s8 < 8; ++s8) {
            const int ks = s8 >> 2, q = s8 & 3;
            if (s8 == 1) {   // prefetch ks=1 A fragments early
                ldsm4(afr[1][0], aA + 32);
                ldsm4(afr[1][1], aA + 16 * STR_B + 32);
            }
            if (s8 < 7) {    // prefetch next B fragment one q-group ahead
                const int ns = s8 + 1, nks = ns >> 2, nq = ns & 3;
                ldsm4(bfr[ns & 1], bA + (uint32_t)(nq * 16 * STR_B + nks * 32));
            }
            const uint32_t* bq = bfr[s8 & 1];
            mma16(acc[0][2 * q],     afr[ks][0], bq[0], bq[1]);
            mma16(acc[0][2 * q + 1], afr[ks][0], bq[2], bq[3]);
            mma16(acc[1][2 * q],     afr[ks][1], bq[0], bq[1]);
            mma16(acc[1][2 * q + 1], afr[ks][1], bq[2], bq[3]);
        }
    }

    // ================= LayerNorm stats =================
    {
        float sums[4] = {0.f, 0.f, 0.f, 0.f}, sqs[4] = {0.f, 0.f, 0.f, 0.f};
#pragma unroll
        for (int mb = 0; mb < 2; ++mb)
#pragma unroll
            for (int q = 0; q < 8; ++q)
#pragma unroll
                for (int c = 0; c < 4; ++c) {
                    const int n = n0w + q * 8 + 2 * (lane & 3) + (c & 1);
                    const float x = acc[mb][q][c] + b1s[n];
                    acc[mb][q][c] = x;
                    const int key = (mb << 1) | (c >> 1);
                    sums[key] += x;
                    sqs[key]  = fmaf(x, x, sqs[key]);
                }
#pragma unroll
        for (int o = 1; o <= 2; o <<= 1)
#pragma unroll
            for (int k = 0; k < 4; ++k) {
                sums[k] += __shfl_xor_sync(0xffffffffu, sums[k], o);
                sqs[k]  += __shfl_xor_sync(0xffffffffu, sqs[k], o);
            }
        if ((lane & 3) == 0) {
#pragma unroll
            for (int k = 0; k < 4; ++k) {
                const int r = m0w + (k >> 1) * 16 + (k & 1) * 8 + (lane >> 2);
                atomicAdd(&rowSum[r], sums[k]);
                atomicAdd(&rowSq[r],  sqs[k]);
            }
        }
    }
    __syncthreads();   // rowSum/rowSq complete; all GEMM1 reads of ring done

    // ---- issue GEMM2 chunks 0,1 NOW (overlap with LN/GELU math below) ----
#pragma unroll
    for (int pg = 0; pg < 2; ++pg) {
        const uint32_t bb = sb + SM_STAGE + (uint32_t)pg * STAGE_BUF + 10240;
        const int kb = pg * KC;
#pragma unroll
        for (int i = 0; i < 2; ++i) {
            const int s = tid + 512 * i, row = s >> 2, seg = s & 3;
            const uint32_t dst = bb + (uint32_t)(row * STR_B + seg * 16);
            if (row < VD) cp16(dst, W2t + (size_t)row * HD + kb + seg * 8);
            else          stz4(dst);
        }
        cpcommit();
    }

    // ================= normalize + exact GELU + store h (fp16) =================
#pragma unroll
    for (int mb = 0; mb < 2; ++mb)
#pragma unroll
        for (int cp = 0; cp < 2; ++cp) {
            const int r = m0w + mb * 16 + cp * 8 + (lane >> 2);
            const float mu   = rowSum[r] * (1.0f / HD);
            const float var  = rowSq[r] * (1.0f / HD) - mu * mu;
            const float rstd = rsqrtf(var + 1e-5f);
#pragma unroll
            for (int q = 0; q < 8; ++q) {
                const int n = n0w + q * 8 + 2 * (lane & 3);
                float y0 = (acc[mb][q][cp * 2]     - mu) * rstd * gms[n]     + bts[n];
                float y1 = (acc[mb][q][cp * 2 + 1] - mu) * rstd * gms[n + 1] + bts[n + 1];
                y0 = 0.5f * y0 * (1.0f + erff(y0 * 0.70710678118654752440f));
                y1 = 0.5f * y1 * (1.0f + erff(y1 * 0.70710678118654752440f));
                sth2(sb + SM_H + (uint32_t)(r * HSTR_B + n * 2), __floats2half2_rn(y0, y1));
            }
        }

    // ================= GEMM2 (16 global chunks = 2 halves x 8) + cosine ==========
    float vc4[4] = {0.f, 0.f, 0.f, 0.f}, vv4[4] = {0.f, 0.f, 0.f, 0.f};

    for (int gc = 0; gc < 16; ++gc) {
        const int kc8 = gc & 7;
        if (gc == 8 || gc == 0) {
            if (gc == 8) {
#pragma unroll
                for (int mb = 0; mb < 2; ++mb)
#pragma unroll
                    for (int q = 0; q < 8; ++q)
#pragma unroll
                        for (int c = 0; c < 4; ++c) {
                            const int n = n0w + q * 8 + 2 * (lane & 3) + (c & 1);
                            const float v = acc[mb][q][c] + b2s[n];
                            const int key = (mb << 1) | (c >> 1);
                            vc4[key] = fmaf(v, cts[n], vc4[key]);
                            vv4[key] = fmaf(v, v,     vv4[key]);
                        }
            }
#pragma unroll
            for (int mb = 0; mb < 2; ++mb)
#pragma unroll
                for (int q = 0; q < 8; ++q)
#pragma unroll
                    for (int c = 0; c < 4; ++c) acc[mb][q][c] = 0.f;
        }
        if (gc < 14) cpwait1(); else cpwait0();
        __syncthreads();
        if (gc + 2 < 16) {
            const int nh = (gc + 2) >> 3, nk = (gc + 2) & 7;
            const uint32_t bb = sb + SM_STAGE + (uint32_t)((gc + 2) % 3) * STAGE_BUF + 10240;
            const int kb = nk * KC;
#pragma unroll
            for (int i = 0; i < 2; ++i) {
                const int s = tid + 512 * i, row = s >> 2, seg = s & 3;
                const int n = nh * 256 + row;
                const uint32_t dst = bb + (uint32_t)(row * STR_B + seg * 16);
                if (n < VD) cp16(dst, W2t + (size_t)n * HD + kb + seg * 8);
                else        stz4(dst);
            }
            cpcommit();
        }
        const uint32_t bb = sb + SM_STAGE + (uint32_t)(gc % 3) * STAGE_BUF + 10240;
        const uint32_t aA = sb + SM_H + hOffW + (uint32_t)(kc8 * KC * 2);
        const uint32_t bA = bb + bOffW;

        uint32_t afr[2][2][4];
        uint32_t bfr[2][4];
        ldsm4(afr[0][0], aA);
        ldsm4(afr[0][1], aA + 16 * HSTR_B);
        ldsm4(bfr[0], bA);
#pragma unroll
        for (int s8 = 0; s8 < 8; ++s8) {
            const int ks = s8 >> 2, q = s8 & 3;
            if (s8 == 1) {
                ldsm4(afr[1][0], aA + 32);
                ldsm4(afr[1][1], aA + 16 * HSTR_B + 32);
            }
            if (s8 < 7) {
                const int ns = s8 + 1, nks = ns >> 2, nq = ns & 3;
                ldsm4(bfr[ns & 1], bA + (uint32_t)(nq * 16 * STR_B + nks * 32));
            }
            const uint32_t* bq = bfr[s8 & 1];
            mma16(acc[0][2 * q],     afr[ks][0], bq[0], bq[1]);
            mma16(acc[0][2 * q + 1], afr[ks][0], bq[2], bq[3]);
            mma16(acc[1][2 * q],     afr[ks][1], bq[0], bq[1]);
            mma16(acc[1][2 * q + 1], afr[ks][1], bq[2], bq[3]);
        }
    }
    // fold half 1
#pragma unroll
    for (int mb = 0; mb < 2; ++mb)
#pragma unroll
        for (int q = 0; q < 8; ++q)
#pragma unroll
            for (int c = 0; c < 4; ++c) {
                const int n = 256 + n0w + q * 8 + 2 * (lane & 3) + (c & 1);
                const float v = acc[mb][q][c] + b2s[n];
                const int key = (mb << 1) | (c >> 1);
                vc4[key] = fmaf(v, cts[n], vc4[key]);
                vv4[key] = fmaf(v, v,     vv4[key]);
            }

#pragma unroll
    for (int o = 1; o <= 2; o <<= 1)
#pragma unroll
        for (int k = 0; k < 4; ++k) {
            vc4[k] += __shfl_xor_sync(0xffffffffu, vc4[k], o);
            vv4[k] += __shfl_xor_sync(0xffffffffu, vv4[k], o);
        }
    if ((lane & 3) == 0) {
#pragma unroll
        for (int k = 0; k < 4; ++k) {
            const int r = m0w + (k >> 1) * 16 + (k & 1) * 8 + (lane >> 2);
            atomicAdd(&vcA[r], vc4[k]);
            atomicAdd(&vvA[r], vv4[k]);
        }
    }
    __syncthreads();

    float dist = 0.f;
    if (tid < 128) {
        float cn2 = 0.f;
#pragma unroll
        for (int i = 0; i < 16; ++i) cn2 += red[i];
        const float cn = fmaxf(sqrtf(cn2), 1e-8f);
        const float vn = fmaxf(sqrtf(vvA[tid]), 1e-8f);
        dist = 1.0f - vcA[tid] / (vn * cn);
    }
#pragma unroll
    for (int o = 16; o > 0; o >>= 1) dist += __shfl_xor_sync(0xffffffffu, dist, o);
    if (tid < 128 && lane == 0) red[16 + wid] = dist;
    __syncthreads();
    if (tid == 0) {
        if (task < out_size)
            atomicAdd(&out[task], red[16] + red[17] + red[18] + red[19]);
        __threadfence();
        const unsigned int old = atomicAdd(&g_count, 1u);
        *flag = (old == (unsigned)(NTASK * (NB / MT) - 1)) ? 1 : 0;
    }
    __syncthreads();

    // ---- last CTA finalizes: scale + argmin ----
    if (*flag) {
        __threadfence();
        float v = 0.0f;
        if (tid < NTASK && tid < out_size) {
            v = out[tid] * (1.0f / (float)NB);
            out[tid] = v;
        }
        if (tid < NTASK) b1s[tid] = v;   // reuse as scratch
        __syncthreads();
        if (tid == 0) {
            int best = 0;
            float bv = b1s[0];
#pragma unroll 1
            for (int i = 1; i < NTASK; ++i)
                if (b1s[i] < bv) { bv = b1s[i]; best = i; }
            if (out_size > 64) out[64] = (float)best;
            g_count = 0u;
        }
    }
}

extern "C" void kernel_launch(void* const* d_in, const int* in_sizes, int n_in,
                              void* d_out, int out_size) {
    const float* t_feat = (const float*)d_in[0];
    const float* W1     = (const float*)d_in[1];
    const float* b1     = (const float*)d_in[2];
    const float* gamma  = (const float*)d_in[3];
    const float* beta   = (const float*)d_in[4];
    const float* W2     = (const float*)d_in[5];
    const float* b2     = (const float*)d_in[6];
    const float* cent   = (const float*)d_in[7];
    float* out = (float*)d_out;

    cudaFuncSetAttribute(router_h16_kernel,
                         cudaFuncAttributeMaxDynamicSharedMemorySize, SMEM_TOTAL);

    convert_kernel<<<2048, 256>>>(t_feat, W1, W2, out, out_size);
    dim3 grid(NB / MT, NTASK);
    router_h16_kernel<<<grid, THREADS, SMEM_TOTAL>>>(
        b1, gamma, beta, b2, cent, out, out_size);
}

// round 12
// speedup vs baseline: 8.1977x; 1.0167x over previous
#include <cuda_runtime.h>
#include <cuda_fp16.h>
#include <cstdint>
#include <math.h>

#define NTASK 64
#define NB    4096
#define TD    512
#define HD    256
#define VD    484
#define MT    64            // batch rows per CTA
#define KC    32            // halves per staged k-chunk
#define THREADS 256

// ---- smem layout (bytes) ----
#define HSTR_B   528
#define SM_H     0
#define SM_H_SZ  (MT * HSTR_B)                  // 33792
#define STR_B    80
#define SM_STAGE SM_H_SZ
#define A_BYTES  (MT * STR_B)                   // 5120
#define STAGE_BUF (A_BYTES + 256 * STR_B)       // 25600
#define SM_PARB  (SM_STAGE + 2 * STAGE_BUF)     // 84992
// params (floats): b1s 256 | gms 256 | bts 256 | b2s 512 | cts 512 |
//                  rowSum 64 | rowSq 64 | vcA 64 | vvA 64 | red 16 | flag 4
#define SMEM_TOTAL (SM_PARB + 2068 * 4)         // 93264

__device__ __half g_tfeat[NB * TD];
__device__ __half g_w1[NTASK * HD * TD];
__device__ __half g_w2[NTASK * VD * HD];
__device__ unsigned int g_count;

__device__ __forceinline__ uint32_t s2u(const void* p) {
    uint32_t a;
    asm("{ .reg .u64 t; cvta.to.shared.u64 t, %1; cvt.u32.u64 %0, t; }" : "=r"(a) : "l"(p));
    return a;
}
__device__ __forceinline__ void cp16(uint32_t dst, const void* src) {
    asm volatile("cp.async.cg.shared.global [%0], [%1], 16;" :: "r"(dst), "l"(src) : "memory");
}
__device__ __forceinline__ void cpcommit() { asm volatile("cp.async.commit_group;" ::: "memory"); }
__device__ __forceinline__ void cpwait1()  { asm volatile("cp.async.wait_group 1;" ::: "memory"); }
__device__ __forceinline__ void cpwait0()  { asm volatile("cp.async.wait_group 0;" ::: "memory"); }

__device__ __forceinline__ void ldsm4(uint32_t* r, uint32_t a) {
    asm volatile("ldmatrix.sync.aligned.m8n8.x4.shared.b16 {%0,%1,%2,%3}, [%4];"
                 : "=r"(r[0]), "=r"(r[1]), "=r"(r[2]), "=r"(r[3]) : "r"(a));
}
__device__ __forceinline__ void mma16(float* c, const uint32_t* a, uint32_t b0, uint32_t b1) {
    asm volatile(
        "mma.sync.aligned.m16n8k16.row.col.f32.f16.f16.f32 "
        "{%0,%1,%2,%3}, {%4,%5,%6,%7}, {%8,%9}, {%0,%1,%2,%3};"
        : "+f"(c[0]), "+f"(c[1]), "+f"(c[2]), "+f"(c[3])
        : "r"(a[0]), "r"(a[1]), "r"(a[2]), "r"(a[3]), "r"(b0), "r"(b1));
}
__device__ __forceinline__ void sth2(uint32_t a, __half2 v) {
    asm volatile("st.shared.b32 [%0], %1;" :: "r"(a), "r"(*(const uint32_t*)&v) : "memory");
}
__device__ __forceinline__ void stz4(uint32_t a) {
    asm volatile("st.shared.v4.b32 [%0], {%1,%1,%1,%1};" :: "r"(a), "r"(0u) : "memory");
}

// ---------------- convert + zero kernel ----------------
__global__ void convert_kernel(const float* __restrict__ t_feat,
                               const float* __restrict__ W1,
                               const float* __restrict__ W2,
                               float* __restrict__ out, int out_size)
{
    const int idx = blockIdx.x * blockDim.x + threadIdx.x;
    const int stride = gridDim.x * blockDim.x;
    if (idx < 65 && idx < out_size) out[idx] = 0.0f;
    for (int i = idx; i < NB * TD / 2; i += stride) {
        const float2 v = ((const float2*)t_feat)[i];
        ((__half2*)g_tfeat)[i] = __floats2half2_rn(v.x, v.y);
    }
    for (int i = idx; i < NTASK * HD * TD / 2; i += stride) {
        const float2 v = ((const float2*)W1)[i];
        ((__half2*)g_w1)[i] = __floats2half2_rn(v.x, v.y);
    }
    for (int i = idx; i < NTASK * VD * HD / 2; i += stride) {
        const float2 v = ((const float2*)W2)[i];
        ((__half2*)g_w2)[i] = __floats2half2_rn(v.x, v.y);
    }
}

// ---------------- main fused kernel (2 CTAs/SM) ----------------
__global__ void __launch_bounds__(THREADS, 2)
router_h16_kernel(const float* __restrict__ b1,
                  const float* __restrict__ gamma,
                  const float* __restrict__ beta,
                  const float* __restrict__ b2,
                  const float* __restrict__ cent,
                  float* __restrict__ out, int out_size)
{
    extern __shared__ char smem[];
    const uint32_t sb = s2u(smem);
    const int tid  = threadIdx.x;
    const int lane = tid & 31;
    const int wid  = tid >> 5;          // 0..7
    const int wm   = wid & 1,  wn = wid >> 1;
    const int m0w  = wm * 32,  n0w = wn * 64;
    const int task = blockIdx.y;
    const int brow0 = blockIdx.x * MT;

    const __half* tA  = g_tfeat + (size_t)brow0 * TD;
    const __half* W1t = g_w1 + (size_t)task * HD * TD;
    const __half* W2t = g_w2 + (size_t)task * VD * HD;

    float* b1s    = (float*)(smem + SM_PARB);
    float* gms    = b1s + 256;
    float* bts    = gms + 256;
    float* b2s    = bts + 256;
    float* cts    = b2s + 512;
    float* rowSum = cts + 512;     // 64
    float* rowSq  = rowSum + 64;   // 64
    float* vcA    = rowSq + 64;    // 64
    float* vvA    = vcA + 64;      // 64
    float* red    = vvA + 64;      // 16
    int*   flag   = (int*)(red + 16);

    // ldmatrix lane addressing (byte offsets within a tile)
    const int arow   = lane & 15;
    const int acol16 = (lane >> 4) * 16;
    const int brow   = (lane & 7) | ((lane >> 4) << 3);
    const int bcol16 = ((lane >> 3) & 1) * 16;
    const uint32_t aOffW = (uint32_t)((m0w + arow) * STR_B + acol16);
    const uint32_t bOffW = (uint32_t)((n0w + brow) * STR_B + bcol16);
    const uint32_t hOffW = (uint32_t)((m0w + arow) * HSTR_B + acol16);

    // staging thread mapping: A = 1 cp16/thread, B = 4 cp16/thread
    const int sArow = tid >> 2, sAseg = tid & 3;

    // ---- prologue: issue GEMM1 chunk 0 ----
    {
        const uint32_t ab = sb + SM_STAGE;
        const uint32_t bb = ab + A_BYTES;
        cp16(ab + (uint32_t)(sArow * STR_B + sAseg * 16), tA + (size_t)sArow * TD + sAseg * 8);
#pragma unroll
        for (int i = 0; i < 4; ++i) {
            const int s = tid + 256 * i, row = s >> 2, seg = s & 3;
            cp16(bb + (uint32_t)(row * STR_B + seg * 16), W1t + (size_t)row * TD + seg * 8);
        }
        cpcommit();
    }

    // ---- params + zeros (overlaps the in-flight cp.async) ----
    if (tid < 256) {
        b1s[tid] = b1[task * HD + tid];
        gms[tid] = gamma[task * HD + tid];
        bts[tid] = beta[task * HD + tid];
    }
    {
        float cc = 0.f;
#pragma unroll
        for (int i = 0; i < 2; ++i) {
            const int n = tid + 256 * i;
            float bv = 0.f, cv = 0.f;
            if (n < VD) { bv = b2[task * VD + n]; cv = cent[task * VD + n]; }
            b2s[n] = bv; cts[n] = cv;
            cc = fmaf(cv, cv, cc);
        }
#pragma unroll
        for (int o = 16; o > 0; o >>= 1) cc += __shfl_xor_sync(0xffffffffu, cc, o);
        if (lane == 0) red[wid] = cc;
    }
    if (tid < 64) { rowSum[tid] = 0.f; rowSq[tid] = 0.f; vcA[tid] = 0.f; vvA[tid] = 0.f; }

    float acc[2][8][4];
#pragma unroll
    for (int mb = 0; mb < 2; ++mb)
#pragma unroll
        for (int q = 0; q < 8; ++q)
#pragma unroll
            for (int c = 0; c < 4; ++c) acc[mb][q][c] = 0.f;

    // ================= GEMM1: 16 chunks, 2-stage ring =================
    for (int c = 0; c < 16; ++c) {
        if (c < 15) {
            const int kb = (c + 1) * KC;
            const uint32_t ab = sb + SM_STAGE + (uint32_t)((c + 1) & 1) * STAGE_BUF;
            const uint32_t bb = ab + A_BYTES;
            cp16(ab + (uint32_t)(sArow * STR_B + sAseg * 16),
                 tA + (size_t)sArow * TD + kb + sAseg * 8);
#pragma unroll
            for (int i = 0; i < 4; ++i) {
                const int s = tid + 256 * i, row = s >> 2, seg = s & 3;
                cp16(bb + (uint32_t)(row * STR_B + seg * 16),
                     W1t + (size_t)row * TD + kb + seg * 8);
            }
            cpcommit();
            cpwait1();
        } else {
            cpwait0();
        }
        __syncthreads();
        const uint32_t ab = sb + SM_STAGE + (uint32_t)(c & 1) * STAGE_BUF;
        const uint32_t aA = ab + aOffW;
        const uint32_t bA = ab + A_BYTES + bOffW;

        uint32_t afr[2][2][4];
        uint32_t bfr[2][4];
        ldsm4(afr[0][0], aA);
        ldsm4(afr[0][1], aA + 16 * STR_B);
        ldsm4(bfr[0], bA);
#pragma unroll
        for (int s8 = 0; s8 < 8; ++s8) {
            const int ks = s8 >> 2, q = s8 & 3;
            if (s8 == 1) {
                ldsm4(afr[1][0], aA + 32);
                ldsm4(afr[1][1], aA + 16 * STR_B + 32);
            }
            if (s8 < 7) {
                const int ns = s8 + 1, nks = ns >> 2, nq = ns & 3;
                ldsm4(bfr[ns & 1], bA + (uint32_t)(nq * 16 * STR_B + nks * 32));
            }
            const uint32_t* bq = bfr[s8 & 1];
            mma16(acc[0][2 * q],     afr[ks][0], bq[0], bq[1]);
            mma16(acc[0][2 * q + 1], afr[ks][0], bq[2], bq[3]);
            mma16(acc[1][2 * q],     afr[ks][1], bq[0], bq[1]);
            mma16(acc[1][2 * q + 1], afr[ks][1], bq[2], bq[3]);
        }
        __syncthreads();
    }

    // ---- issue GEMM2 chunk 0 (overlaps LN/GELU below) ----
    {
        const uint32_t bb = sb + SM_STAGE + A_BYTES;
#pragma unroll
        for (int i = 0; i < 4; ++i) {
            const int s = tid + 256 * i, row = s >> 2, seg = s & 3;
            const uint32_t dst = bb + (uint32_t)(row * STR_B + seg * 16);
            if (row < VD) cp16(dst, W2t + (size_t)row * HD + seg * 8);
            else          stz4(dst);
        }
        cpcommit();
    }

    // ================= LayerNorm stats =================
    {
        float sums[4] = {0.f, 0.f, 0.f, 0.f}, sqs[4] = {0.f, 0.f, 0.f, 0.f};
#pragma unroll
        for (int mb = 0; mb < 2; ++mb)
#pragma unroll
            for (int q = 0; q < 8; ++q)
#pragma unroll
                for (int c = 0; c < 4; ++c) {
                    const int n = n0w + q * 8 + 2 * (lane & 3) + (c & 1);
                    const float x = acc[mb][q][c] + b1s[n];
                    acc[mb][q][c] = x;
                    const int key = (mb << 1) | (c >> 1);
                    sums[key] += x;
                    sqs[key]  = fmaf(x, x, sqs[key]);
                }
#pragma unroll
        for (int o = 1; o <= 2; o <<= 1)
#pragma unroll
            for (int k = 0; k < 4; ++k) {
                sums[k] += __shfl_xor_sync(0xffffffffu, sums[k], o);
                sqs[k]  += __shfl_xor_sync(0xffffffffu, sqs[k], o);
            }
        if ((lane & 3) == 0) {
#pragma unroll
            for (int k = 0; k < 4; ++k) {
                const int r = m0w + (k >> 1) * 16 + (k & 1) * 8 + (lane >> 2);
                atomicAdd(&rowSum[r], sums[k]);
                atomicAdd(&rowSq[r],  sqs[k]);
            }
        }
    }
    __syncthreads();

    // ================= normalize + exact GELU + store h (fp16) =================
#pragma unroll
    for (int mb = 0; mb < 2; ++mb)
#pragma unroll
        for (int cp = 0; cp < 2; ++cp) {
            const int r = m0w + mb * 16 + cp * 8 + (lane >> 2);
            const float mu   = rowSum[r] * (1.0f / HD);
            const float var  = rowSq[r] * (1.0f / HD) - mu * mu;
            const float rstd = rsqrtf(var + 1e-5f);
#pragma unroll
            for (int q = 0; q < 8; ++q) {
                const int n = n0w + q * 8 + 2 * (lane & 3);
                float y0 = (acc[mb][q][cp * 2]     - mu) * rstd * gms[n]     + bts[n];
                float y1 = (acc[mb][q][cp * 2 + 1] - mu) * rstd * gms[n + 1] + bts[n + 1];
                y0 = 0.5f * y0 * (1.0f + erff(y0 * 0.70710678118654752440f));
                y1 = 0.5f * y1 * (1.0f + erff(y1 * 0.70710678118654752440f));
                sth2(sb + SM_H + (uint32_t)(r * HSTR_B + n * 2), __floats2half2_rn(y0, y1));
            }
        }

    // ================= GEMM2 (16 chunks = 2 halves x 8) + cosine ==========
    float vc4[4] = {0.f, 0.f, 0.f, 0.f}, vv4[4] = {0.f, 0.f, 0.f, 0.f};

    for (int gc = 0; gc < 16; ++gc) {
        const int kc8 = gc & 7;
        if (gc == 8 || gc == 0) {
            if (gc == 8) {
#pragma unroll
                for (int mb = 0; mb < 2; ++mb)
#pragma unroll
                    for (int q = 0; q < 8; ++q)
#pragma unroll
                        for (int c = 0; c < 4; ++c) {
                            const int n = n0w + q * 8 + 2 * (lane & 3) + (c & 1);
                            const float v = acc[mb][q][c] + b2s[n];
                            const int key = (mb << 1) | (c >> 1);
                            vc4[key] = fmaf(v, cts[n], vc4[key]);
                            vv4[key] = fmaf(v, v,     vv4[key]);
                        }
            }
#pragma unroll
            for (int mb = 0; mb < 2; ++mb)
#pragma unroll
                for (int q = 0; q < 8; ++q)
#pragma unroll
                    for (int c = 0; c < 4; ++c) acc[mb][q][c] = 0.f;
        }
        if (gc < 15) {
            const int nh = (gc + 1) >> 3, nk = (gc + 1) & 7;
            const uint32_t bb = sb + SM_STAGE + (uint32_t)((gc + 1) & 1) * STAGE_BUF + A_BYTES;
            const int kb = nk * KC;
#pragma unroll
            for (int i = 0; i < 4; ++i) {
                const int s = tid + 256 * i, row = s >> 2, seg = s & 3;
                const int n = nh * 256 + row;
                const uint32_t dst = bb + (uint32_t)(row * STR_B + seg * 16);
                if (n < VD) cp16(dst, W2t + (size_t)n * HD + kb + seg * 8);
                else        stz4(dst);
            }
            cpcommit();
            cpwait1();
        } else {
            cpwait0();
        }
        __syncthreads();
        const uint32_t bb = sb + SM_STAGE + (uint32_t)(gc & 1) * STAGE_BUF + A_BYTES;
        const uint32_t aA = sb + SM_H + hOffW + (uint32_t)(kc8 * KC * 2);
        const uint32_t bA = bb + bOffW;

        uint32_t afr[2][2][4];
        uint32_t bfr[2][4];
        ldsm4(afr[0][0], aA);
        ldsm4(afr[0][1], aA + 16 * HSTR_B);
        ldsm4(bfr[0], bA);
#pragma unroll
        for (int s8 = 0; s8 < 8; ++s8) {
            const int ks = s8 >> 2, q = s8 & 3;
            if (s8 == 1) {
                ldsm4(afr[1][0], aA + 32);
                ldsm4(afr[1][1], aA + 16 * HSTR_B + 32);
            }
            if (s8 < 7) {
                const int ns = s8 + 1, nks = ns >> 2, nq = ns & 3;
                ldsm4(bfr[ns & 1], bA + (uint32_t)(nq * 16 * STR_B + nks * 32));
            }
            const uint32_t* bq = bfr[s8 & 1];
            mma16(acc[0][2 * q],     afr[ks][0], bq[0], bq[1]);
            mma16(acc[0][2 * q + 1], afr[ks][0], bq[2], bq[3]);
            mma16(acc[1][2 * q],     afr[ks][1], bq[0], bq[1]);
            mma16(acc[1][2 * q + 1], afr[ks][1], bq[2], bq[3]);
        }
        __syncthreads();
    }
    // fold half 1
#pragma unroll
    for (int mb = 0; mb < 2; ++mb)
#pragma unroll
        for (int q = 0; q < 8; ++q)
#pragma unroll
            for (int c = 0; c < 4; ++c) {
                const int n = 256 + n0w + q * 8 + 2 * (lane & 3) + (c & 1);
                const float v = acc[mb][q][c] + b2s[n];
                const int key = (mb << 1) | (c >> 1);
                vc4[key] = fmaf(v, cts[n], vc4[key]);
                vv4[key] = fmaf(v, v,     vv4[key]);
            }

#pragma unroll
    for (int o = 1; o <= 2; o <<= 1)
#pragma unroll
        for (int k = 0; k < 4; ++k) {
            vc4[k] += __shfl_xor_sync(0xffffffffu, vc4[k], o);
            vv4[k] += __shfl_xor_sync(0xffffffffu, vv4[k], o);
        }
    if ((lane & 3) == 0) {
#pragma unroll
        for (int k = 0; k < 4; ++k) {
            const int r = m0w + (k >> 1) * 16 + (k & 1) * 8 + (lane >> 2);
            atomicAdd(&vcA[r], vc4[k]);
            atomicAdd(&vvA[r], vv4[k]);
        }
    }
    __syncthreads();

    float dist = 0.f;
    if (tid < 64) {
        float cn2 = 0.f;
#pragma unroll
        for (int i = 0; i < 8; ++i) cn2 += red[i];
        const float cn = fmaxf(sqrtf(cn2), 1e-8f);
        const float vn = fmaxf(sqrtf(vvA[tid]), 1e-8f);
        dist = 1.0f - vcA[tid] / (vn * cn);
    }
#pragma unroll
    for (int o = 16; o > 0; o >>= 1) dist += __shfl_xor_sync(0xffffffffu, dist, o);
    if (tid < 64 && lane == 0) red[8 + wid] = dist;
    __syncthreads();
    if (tid == 0) {
        if (task < out_size)
            atomicAdd(&out[task], red[8] + red[9]);
        __threadfence();
        const unsigned int old = atomicAdd(&g_count, 1u);
        *flag = (old == (unsigned)(NTASK * (NB / MT) - 1)) ? 1 : 0;
    }
    __syncthreads();

    // ---- last CTA finalizes: scale + argmin ----
    if (*flag) {
        __threadfence();
        float v = 0.0f;
        if (tid < NTASK && tid < out_size) {
            v = out[tid] * (1.0f / (float)NB);
            out[tid] = v;
        }
        if (tid < NTASK) b1s[tid] = v;   // reuse as scratch
        __syncthreads();
        if (tid == 0) {
            int best = 0;
            float bv = b1s[0];
#pragma unroll 1
            for (int i = 1; i < NTASK; ++i)
                if (b1s[i] < bv) { bv = b1s[i]; best = i; }
            if (out_size > 64) out[64] = (float)best;
            g_count = 0u;
        }
    }
}

extern "C" void kernel_launch(void* const* d_in, const int* in_sizes, int n_in,
                              void* d_out, int out_size) {
    const float* t_feat = (const float*)d_in[0];
    const float* W1     = (const float*)d_in[1];
    const float* b1     = (const float*)d_in[2];
    const float* gamma  = (const float*)d_in[3];
    const float* beta   = (const float*)d_in[4];
    const float* W2     = (const float*)d_in[5];
    const float* b2     = (const float*)d_in[6];
    const float* cent   = (const float*)d_in[7];
    float* out = (float*)d_out;

    cudaFuncSetAttribute(router_h16_kernel,
                         cudaFuncAttributeMaxDynamicSharedMemorySize, SMEM_TOTAL);

    convert_kernel<<<2048, 256>>>(t_feat, W1, W2, out, out_size);
    dim3 grid(NB / MT, NTASK);
    router_h16_kernel<<<grid, THREADS, SMEM_TOTAL>>>(
        b1, gamma, beta, b2, cent, out, out_size);
}

// round 13
// speedup vs baseline: 8.2090x; 1.0014x over previous
#include <cuda_runtime.h>
#include <cuda_fp16.h>
#include <cstdint>
#include <math.h>

#define NTASK 64
#define NB    4096
#define TD    512
#define HD    256
#define VD    484
#define MT    64            // batch rows per CTA
#define KC    32            // halves per staged k-chunk
#define THREADS 128

// ---- smem layout (bytes) ----
#define HSTR_B   528
#define SM_H     0
#define SM_H_SZ  (MT * HSTR_B)                  // 33792
#define STR_B    80
#define SM_STAGE SM_H_SZ
#define A_BYTES  (MT * STR_B)                   // 5120
#define STAGE_BUF (A_BYTES + 256 * STR_B)       // 25600
#define SM_PARB  (SM_STAGE + 2 * STAGE_BUF)     // 84992
// params (floats): b1s 256 | gms 256 | bts 256 | b2s 512 | cts 512 |
//                  rowSum 64 | rowSq 64 | vcA 64 | vvA 64 | red 8 | flag
#define SMEM_TOTAL (SM_PARB + 2060 * 4)         // 93232

__device__ __half g_tfeat[NB * TD];
__device__ __half g_w1[NTASK * HD * TD];
__device__ __half g_w2[NTASK * VD * HD];
__device__ unsigned int g_count;

__device__ __forceinline__ uint32_t s2u(const void* p) {
    uint32_t a;
    asm("{ .reg .u64 t; cvta.to.shared.u64 t, %1; cvt.u32.u64 %0, t; }" : "=r"(a) : "l"(p));
    return a;
}
__device__ __forceinline__ void cp16(uint32_t dst, const void* src) {
    asm volatile("cp.async.cg.shared.global [%0], [%1], 16;" :: "r"(dst), "l"(src) : "memory");
}
__device__ __forceinline__ void cpcommit() { asm volatile("cp.async.commit_group;" ::: "memory"); }
__device__ __forceinline__ void cpwait1()  { asm volatile("cp.async.wait_group 1;" ::: "memory"); }
__device__ __forceinline__ void cpwait0()  { asm volatile("cp.async.wait_group 0;" ::: "memory"); }

__device__ __forceinline__ void ldsm4(uint32_t* r, uint32_t a) {
    asm volatile("ldmatrix.sync.aligned.m8n8.x4.shared.b16 {%0,%1,%2,%3}, [%4];"
                 : "=r"(r[0]), "=r"(r[1]), "=r"(r[2]), "=r"(r[3]) : "r"(a));
}
__device__ __forceinline__ void mma16(float* c, const uint32_t* a, uint32_t b0, uint32_t b1) {
    asm volatile(
        "mma.sync.aligned.m16n8k16.row.col.f32.f16.f16.f32 "
        "{%0,%1,%2,%3}, {%4,%5,%6,%7}, {%8,%9}, {%0,%1,%2,%3};"
        : "+f"(c[0]), "+f"(c[1]), "+f"(c[2]), "+f"(c[3])
        : "r"(a[0]), "r"(a[1]), "r"(a[2]), "r"(a[3]), "r"(b0), "r"(b1));
}
__device__ __forceinline__ void sth2(uint32_t a, __half2 v) {
    asm volatile("st.shared.b32 [%0], %1;" :: "r"(a), "r"(*(const uint32_t*)&v) : "memory");
}
__device__ __forceinline__ void stz4(uint32_t a) {
    asm volatile("st.shared.v4.b32 [%0], {%1,%1,%1,%1};" :: "r"(a), "r"(0u) : "memory");
}

// ---------------- convert + zero kernel ----------------
__global__ void convert_kernel(const float* __restrict__ t_feat,
                               const float* __restrict__ W1,
                               const float* __restrict__ W2,
                               float* __restrict__ out, int out_size)
{
    const int idx = blockIdx.x * blockDim.x + threadIdx.x;
    const int stride = gridDim.x * blockDim.x;
    if (idx < 65 && idx < out_size) out[idx] = 0.0f;
    for (int i = idx; i < NB * TD / 2; i += stride) {
        const float2 v = ((const float2*)t_feat)[i];
        ((__half2*)g_tfeat)[i] = __floats2half2_rn(v.x, v.y);
    }
    for (int i = idx; i < NTASK * HD * TD / 2; i += stride) {
        const float2 v = ((const float2*)W1)[i];
        ((__half2*)g_w1)[i] = __floats2half2_rn(v.x, v.y);
    }
    for (int i = idx; i < NTASK * VD * HD / 2; i += stride) {
        const float2 v = ((const float2*)W2)[i];
        ((__half2*)g_w2)[i] = __floats2half2_rn(v.x, v.y);
    }
}

// ---------------- main fused kernel (4 warps, 64x64 warp tiles, 2 CTA/SM) ------
__global__ void __launch_bounds__(THREADS, 2)
router_h16_kernel(const float* __restrict__ b1,
                  const float* __restrict__ gamma,
                  const float* __restrict__ beta,
                  const float* __restrict__ b2,
                  const float* __restrict__ cent,
                  float* __restrict__ out, int out_size)
{
    extern __shared__ char smem[];
    const uint32_t sb = s2u(smem);
    const int tid  = threadIdx.x;
    const int lane = tid & 31;
    const int wid  = tid >> 5;          // 0..3
    const int n0w  = wid * 64;          // warp covers all 64 rows x 64 cols
    const int task = blockIdx.y;
    const int brow0 = blockIdx.x * MT;

    const __half* tA  = g_tfeat + (size_t)brow0 * TD;
    const __half* W1t = g_w1 + (size_t)task * HD * TD;
    const __half* W2t = g_w2 + (size_t)task * VD * HD;

    float* b1s    = (float*)(smem + SM_PARB);
    float* gms    = b1s + 256;
    float* bts    = gms + 256;
    float* b2s    = bts + 256;
    float* cts    = b2s + 512;
    float* rowSum = cts + 512;     // 64
    float* rowSq  = rowSum + 64;   // 64
    float* vcA    = rowSq + 64;    // 64
    float* vvA    = vcA + 64;      // 64
    float* red    = vvA + 64;      // 8
    int*   flag   = (int*)(red + 8);

    // ldmatrix lane addressing (byte offsets)
    const int arow   = lane & 15;
    const int acol16 = (lane >> 4) * 16;
    const int brow   = (lane & 7) | ((lane >> 4) << 3);
    const int bcol16 = ((lane >> 3) & 1) * 16;
    const uint32_t aOffW = (uint32_t)(arow * STR_B + acol16);
    const uint32_t bOffW = (uint32_t)((n0w + brow) * STR_B + bcol16);
    const uint32_t hOffW = (uint32_t)(arow * HSTR_B + acol16);

    // staging thread mapping (128 threads)
    // ---- prologue: issue GEMM1 chunk 0 ----
    {
        const uint32_t ab = sb + SM_STAGE;
        const uint32_t bb = ab + A_BYTES;
#pragma unroll
        for (int i = 0; i < 2; ++i) {
            const int s = tid + 128 * i, row = s >> 2, seg = s & 3;
            cp16(ab + (uint32_t)(row * STR_B + seg * 16), tA + (size_t)row * TD + seg * 8);
        }
#pragma unroll
        for (int i = 0; i < 8; ++i) {
            const int s = tid + 128 * i, row = s >> 2, seg = s & 3;
            cp16(bb + (uint32_t)(row * STR_B + seg * 16), W1t + (size_t)row * TD + seg * 8);
        }
        cpcommit();
    }

    // ---- params + zeros ----
#pragma unroll
    for (int i = 0; i < 2; ++i) {
        const int n = tid + 128 * i;
        b1s[n] = b1[task * HD + n];
        gms[n] = gamma[task * HD + n];
        bts[n] = beta[task * HD + n];
    }
    {
        float cc = 0.f;
#pragma unroll
        for (int i = 0; i < 4; ++i) {
            const int n = tid + 128 * i;
            float bv = 0.f, cv = 0.f;
            if (n < VD) { bv = b2[task * VD + n]; cv = cent[task * VD + n]; }
            b2s[n] = bv; cts[n] = cv;
            cc = fmaf(cv, cv, cc);
        }
#pragma unroll
        for (int o = 16; o > 0; o >>= 1) cc += __shfl_xor_sync(0xffffffffu, cc, o);
        if (lane == 0) red[wid] = cc;
    }
    if (tid < 64) { rowSum[tid] = 0.f; rowSq[tid] = 0.f; vcA[tid] = 0.f; vvA[tid] = 0.f; }

    float acc[4][8][4];
#pragma unroll
    for (int mb = 0; mb < 4; ++mb)
#pragma unroll
        for (int q = 0; q < 8; ++q)
#pragma unroll
            for (int c = 0; c < 4; ++c) acc[mb][q][c] = 0.f;

    // ================= GEMM1: 16 chunks, 2-stage ring =================
    for (int c = 0; c < 16; ++c) {
        if (c < 15) {
            const int kb = (c + 1) * KC;
            const uint32_t ab = sb + SM_STAGE + (uint32_t)((c + 1) & 1) * STAGE_BUF;
            const uint32_t bb = ab + A_BYTES;
#pragma unroll
            for (int i = 0; i < 2; ++i) {
                const int s = tid + 128 * i, row = s >> 2, seg = s & 3;
                cp16(ab + (uint32_t)(row * STR_B + seg * 16),
                     tA + (size_t)row * TD + kb + seg * 8);
            }
#pragma unroll
            for (int i = 0; i < 8; ++i) {
                const int s = tid + 128 * i, row = s >> 2, seg = s & 3;
                cp16(bb + (uint32_t)(row * STR_B + seg * 16),
                     W1t + (size_t)row * TD + kb + seg * 8);
            }
            cpcommit();
            cpwait1();
        } else {
            cpwait0();
        }
        __syncthreads();
        const uint32_t ab = sb + SM_STAGE + (uint32_t)(c & 1) * STAGE_BUF;
        const uint32_t aA = ab + aOffW;
        const uint32_t bA = ab + A_BYTES + bOffW;

        uint32_t afr[2][4][4];   // [ks][mb]
        uint32_t bfr[2][4];
#pragma unroll
        for (int mb = 0; mb < 4; ++mb) ldsm4(afr[0][mb], aA + (uint32_t)(mb * 16 * STR_B));
        ldsm4(bfr[0], bA);
#pragma unroll
        for (int ks = 0; ks < 2; ++ks)
#pragma unroll
            for (int q4 = 0; q4 < 4; ++q4) {
                const int s = ks * 4 + q4;
                if (ks == 0)   // prefetch ks=1 A fragment (used from s=4)
                    ldsm4(afr[1][q4], aA + (uint32_t)(q4 * 16 * STR_B + 32));
                if (s < 7) {
                    const int ns = s + 1, nks = ns >> 2, nq = ns & 3;
                    ldsm4(bfr[ns & 1], bA + (uint32_t)(nq * 16 * STR_B + nks * 32));
                }
                const uint32_t* bq = bfr[s & 1];
#pragma unroll
                for (int mb = 0; mb < 4; ++mb) {
                    mma16(acc[mb][2 * q4],     afr[ks][mb], bq[0], bq[1]);
                    mma16(acc[mb][2 * q4 + 1], afr[ks][mb], bq[2], bq[3]);
                }
            }
        __syncthreads();
    }

    // ---- issue GEMM2 chunk 0 (overlaps LN/GELU below) ----
    {
        const uint32_t bb = sb + SM_STAGE + A_BYTES;
#pragma unroll
        for (int i = 0; i < 8; ++i) {
            const int s = tid + 128 * i, row = s >> 2, seg = s & 3;
            const uint32_t dst = bb + (uint32_t)(row * STR_B + seg * 16);
            if (row < VD) cp16(dst, W2t + (size_t)row * HD + seg * 8);
            else          stz4(dst);
        }
        cpcommit();
    }

    // ================= LayerNorm stats =================
    {
        float sums[8], sqs[8];
#pragma unroll
        for (int k = 0; k < 8; ++k) { sums[k] = 0.f; sqs[k] = 0.f; }
#pragma unroll
        for (int mb = 0; mb < 4; ++mb)
#pragma unroll
            for (int q = 0; q < 8; ++q)
#pragma unroll
                for (int c = 0; c < 4; ++c) {
                    const int n = n0w + q * 8 + 2 * (lane & 3) + (c & 1);
                    const float x = acc[mb][q][c] + b1s[n];
                    acc[mb][q][c] = x;
                    const int key = (mb << 1) | (c >> 1);
                    sums[key] += x;
                    sqs[key]  = fmaf(x, x, sqs[key]);
                }
#pragma unroll
        for (int o = 1; o <= 2; o <<= 1)
#pragma unroll
            for (int k = 0; k < 8; ++k) {
                sums[k] += __shfl_xor_sync(0xffffffffu, sums[k], o);
                sqs[k]  += __shfl_xor_sync(0xffffffffu, sqs[k], o);
            }
        if ((lane & 3) == 0) {
#pragma unroll
            for (int k = 0; k < 8; ++k) {
                const int r = (k >> 1) * 16 + (k & 1) * 8 + (lane >> 2);
                atomicAdd(&rowSum[r], sums[k]);
                atomicAdd(&rowSq[r],  sqs[k]);
            }
        }
    }
    __syncthreads();

    // ================= normalize + exact GELU + store h (fp16) =================
#pragma unroll
    for (int mb = 0; mb < 4; ++mb)
#pragma unroll
        for (int cp = 0; cp < 2; ++cp) {
            const int r = mb * 16 + cp * 8 + (lane >> 2);
            const float mu   = rowSum[r] * (1.0f / HD);
            const float var  = rowSq[r] * (1.0f / HD) - mu * mu;
            const float rstd = rsqrtf(var + 1e-5f);
#pragma unroll
            for (int q = 0; q < 8; ++q) {
                const int n = n0w + q * 8 + 2 * (lane & 3);
                float y0 = (acc[mb][q][cp * 2]     - mu) * rstd * gms[n]     + bts[n];
                float y1 = (acc[mb][q][cp * 2 + 1] - mu) * rstd * gms[n + 1] + bts[n + 1];
                y0 = 0.5f * y0 * (1.0f + erff(y0 * 0.70710678118654752440f));
                y1 = 0.5f * y1 * (1.0f + erff(y1 * 0.70710678118654752440f));
                sth2(sb + SM_H + (uint32_t)(r * HSTR_B + n * 2), __floats2half2_rn(y0, y1));
            }
        }

    // ================= GEMM2 (16 chunks = 2 halves x 8) + cosine ==========
    float vc4[8], vv4[8];
#pragma unroll
    for (int k = 0; k < 8; ++k) { vc4[k] = 0.f; vv4[k] = 0.f; }

    for (int gc = 0; gc < 16; ++gc) {
        const int kc8 = gc & 7;
        if (gc == 8 || gc == 0) {
            if (gc == 8) {
#pragma unroll
                for (int mb = 0; mb < 4; ++mb)
#pragma unroll
                    for (int q = 0; q < 8; ++q)
#pragma unroll
                        for (int c = 0; c < 4; ++c) {
                            const int n = n0w + q * 8 + 2 * (lane & 3) + (c & 1);
                            const float v = acc[mb][q][c] + b2s[n];
                            const int key = (mb << 1) | (c >> 1);
                            vc4[key] = fmaf(v, cts[n], vc4[key]);
                            vv4[key] = fmaf(v, v,     vv4[key]);
                        }
            }
#pragma unroll
            for (int mb = 0; mb < 4; ++mb)
#pragma unroll
                for (int q = 0; q < 8; ++q)
#pragma unroll
                    for (int c = 0; c < 4; ++c) acc[mb][q][c] = 0.f;
        }
        if (gc < 15) {
            const int nh = (gc + 1) >> 3, nk = (gc + 1) & 7;
            const uint32_t bb = sb + SM_STAGE + (uint32_t)((gc + 1) & 1) * STAGE_BUF + A_BYTES;
            const int kb = nk * KC;
#pragma unroll
            for (int i = 0; i < 8; ++i) {
                const int s = tid + 128 * i, row = s >> 2, seg = s & 3;
                const int n = nh * 256 + row;
                const uint32_t dst = bb + (uint32_t)(row * STR_B + seg * 16);
                if (n < VD) cp16(dst, W2t + (size_t)n * HD + kb + seg * 8);
                else        stz4(dst);
            }
            cpcommit();
            cpwait1();
        } else {
            cpwait0();
        }
        __syncthreads();
        const uint32_t aA = sb + SM_H + hOffW + (uint32_t)(kc8 * KC * 2);
        const uint32_t bA = sb + SM_STAGE + (uint32_t)(gc & 1) * STAGE_BUF + A_BYTES + bOffW;

        uint32_t afr[2][4][4];
        uint32_t bfr[2][4];
#pragma unroll
        for (int mb = 0; mb < 4; ++mb) ldsm4(afr[0][mb], aA + (uint32_t)(mb * 16 * HSTR_B));
        ldsm4(bfr[0], bA);
#pragma unroll
        for (int ks = 0; ks < 2; ++ks)
#pragma unroll
            for (int q4 = 0; q4 < 4; ++q4) {
                const int s = ks * 4 + q4;
                if (ks == 0)
                    ldsm4(afr[1][q4], aA + (uint32_t)(q4 * 16 * HSTR_B + 32));
                if (s < 7) {
                    const int ns = s + 1, nks = ns >> 2, nq = ns & 3;
                    ldsm4(bfr[ns & 1], bA + (uint32_t)(nq * 16 * STR_B + nks * 32));
                }
                const uint32_t* bq = bfr[s & 1];
#pragma unroll
                for (int mb = 0; mb < 4; ++mb) {
                    mma16(acc[mb][2 * q4],     afr[ks][mb], bq[0], bq[1]);
                    mma16(acc[mb][2 * q4 + 1], afr[ks][mb], bq[2], bq[3]);
                }
            }
        __syncthreads();
    }
    // fold half 1
#pragma unroll
    for (int mb = 0; mb < 4; ++mb)
#pragma unroll
        for (int q = 0; q < 8; ++q)
#pragma unroll
            for (int c = 0; c < 4; ++c) {
                const int n = 256 + n0w + q * 8 + 2 * (lane & 3) + (c & 1);
                const float v = acc[mb][q][c] + b2s[n];
                const int key = (mb << 1) | (c >> 1);
                vc4[key] = fmaf(v, cts[n], vc4[key]);
                vv4[key] = fmaf(v, v,     vv4[key]);
            }

#pragma unroll
    for (int o = 1; o <= 2; o <<= 1)
#pragma unroll
        for (int k = 0; k < 8; ++k) {
            vc4[k] += __shfl_xor_sync(0xffffffffu, vc4[k], o);
            vv4[k] += __shfl_xor_sync(0xffffffffu, vv4[k], o);
        }
    if ((lane & 3) == 0) {
#pragma unroll
        for (int k = 0; k < 8; ++k) {
            const int r = (k >> 1) * 16 + (k & 1) * 8 + (lane >> 2);
            atomicAdd(&vcA[r], vc4[k]);
            atomicAdd(&vvA[r], vv4[k]);
        }
    }
    __syncthreads();

    float dist = 0.f;
    if (tid < 64) {
        float cn2 = red[0] + red[1] + red[2] + red[3];
        const float cn = fmaxf(sqrtf(cn2), 1e-8f);
        const float vn = fmaxf(sqrtf(vvA[tid]), 1e-8f);
        dist = 1.0f - vcA[tid] / (vn * cn);
    }
#pragma unroll
    for (int o = 16; o > 0; o >>= 1) dist += __shfl_xor_sync(0xffffffffu, dist, o);
    if (tid < 64 && lane == 0) red[4 + wid] = dist;
    __syncthreads();
    if (tid == 0) {
        if (task < out_size)
            atomicAdd(&out[task], red[4] + red[5]);
        __threadfence();
        const unsigned int old = atomicAdd(&g_count, 1u);
        *flag = (old == (unsigned)(NTASK * (NB / MT) - 1)) ? 1 : 0;
    }
    __syncthreads();

    // ---- last CTA finalizes: scale + argmin ----
    if (*flag) {
        __threadfence();
        float v = 0.0f;
        if (tid < NTASK && tid < out_size) {
            v = out[tid] * (1.0f / (float)NB);
            out[tid] = v;
        }
        if (tid < NTASK) b1s[tid] = v;   // reuse as scratch
        __syncthreads();
        if (tid == 0) {
            int best = 0;
            float bv = b1s[0];
#pragma unroll 1
            for (int i = 1; i < NTASK; ++i)
                if (b1s[i] < bv) { bv = b1s[i]; best = i; }
            if (out_size > 64) out[64] = (float)best;
            g_count = 0u;
        }
    }
}

extern "C" void kernel_launch(void* const* d_in, const int* in_sizes, int n_in,
                              void* d_out, int out_size) {
    const float* t_feat = (const float*)d_in[0];
    const float* W1     = (const float*)d_in[1];
    const float* b1     = (const float*)d_in[2];
    const float* gamma  = (const float*)d_in[3];
    const float* beta   = (const float*)d_in[4];
    const float* W2     = (const float*)d_in[5];
    const float* b2     = (const float*)d_in[6];
    const float* cent   = (const float*)d_in[7];
    float* out = (float*)d_out;

    cudaFuncSetAttribute(router_h16_kernel,
                         cudaFuncAttributeMaxDynamicSharedMemorySize, SMEM_TOTAL);

    convert_kernel<<<2048, 256>>>(t_feat, W1, W2, out, out_size);
    dim3 grid(NB / MT, NTASK);
    router_h16_kernel<<<grid, THREADS, SMEM_TOTAL>>>(
        b1, gamma, beta, b2, cent, out, out_size);
}